// round 2
// baseline (speedup 1.0000x reference)
#include <cuda_runtime.h>
#include <math.h>
#include <float.h>

#define TT 2048
#define HIDDEN 2048
#define NH 32
#define NKV 4
#define HD 128
#define QS (NH*HD)        // 4096
#define KVS (NKV*HD)      // 512
#define QKVN (QS + 2*KVS) // 5120

// ---------------- scratch (static device globals; no allocs) ----------------
__device__ float g_qkv [(size_t)TT * QKVN];     //  40 MB
__device__ float g_q   [(size_t)NH * TT * HD];  //  32 MB  [h][t][d]
__device__ float g_k   [(size_t)NKV * TT * HD]; //   4 MB  [kv][t][d]
__device__ float g_vt  [(size_t)NKV * HD * TT]; //   4 MB  [kv][d][t] (transposed)
__device__ float g_s   [(size_t)NH * TT * TT];  // 536 MB  [h][q][k]
__device__ float g_attn[(size_t)TT * QS];       //  32 MB  [t][h*128+d]
__device__ float g_invf[64];

// ---------------- helpers ----------------
__device__ __forceinline__ float tf32r(float x) {
    unsigned o;
    asm("cvt.rna.tf32.f32 %0, %1;" : "=r"(o) : "f"(x));
    return __uint_as_float(o);
}

__device__ __forceinline__ void mma_tf32(float* d, const unsigned* a, const unsigned* b) {
    asm volatile(
        "mma.sync.aligned.m16n8k8.row.col.f32.tf32.tf32.f32 "
        "{%0,%1,%2,%3}, {%4,%5,%6,%7}, {%8,%9}, {%0,%1,%2,%3};\n"
        : "+f"(d[0]), "+f"(d[1]), "+f"(d[2]), "+f"(d[3])
        : "r"(a[0]), "r"(a[1]), "r"(a[2]), "r"(a[3]), "r"(b[0]), "r"(b[1]));
}

// ---------------- generic TN GEMM: C[M,N] = A[M,K] * B[N,K]^T ----------------
// mode 0: plain; mode 1: S-mode (skip blocks with bn>bm, causal-triangular);
// mode 2: PV-mode (k-loop limited to (bm+1)*128, causal)
// batch z: A += z*sA; B += (z>>bShift)*sB; C += z*sC
#define BM 128
#define BN 128
#define BK 32

__global__ __launch_bounds__(256) void gemm_tn(
    const float* __restrict__ A, const float* __restrict__ B, float* __restrict__ C,
    int M, int N, int K, int lda, int ldb, int ldc,
    long long sA, long long sB, long long sC, int bShift,
    float scale, int mode)
{
    int bm = blockIdx.y, bn = blockIdx.x, z = blockIdx.z;
    if (mode == 1 && bn > bm) return;

    A += (long long)z * sA;
    B += (long long)(z >> bShift) * sB;
    C += (long long)z * sC;

    __shared__ float As[BK][BM + 1]; // [k][m], stride 129 -> conflict-free STS
    __shared__ float Bs[BK][BN + 1]; // [k][n]

    int tid  = threadIdx.x;
    int warp = tid >> 5, lane = tid & 31;
    int wm = warp & 3, wn = warp >> 2;   // 4 x 2 warp grid (m x n)
    int c  = lane & 3, r  = lane >> 2;

    float acc[2][8][4];
#pragma unroll
    for (int i = 0; i < 2; i++)
#pragma unroll
        for (int j = 0; j < 8; j++)
#pragma unroll
            for (int k = 0; k < 4; k++) acc[i][j][k] = 0.f;

    int kmax = (mode == 2) ? min(K, (bm + 1) * BM) : K;
    const float* Ab = A + (long long)bm * BM * lda;
    const float* Bb = B + (long long)bn * BN * ldb;

    for (int kb = 0; kb < kmax; kb += BK) {
#pragma unroll
        for (int i = 0; i < 4; i++) {
            int li = tid + i * 256;      // 1024 float4 total per operand
            int m  = li >> 3;
            int kq = (li & 7) << 2;
            float4 va = *(const float4*)(Ab + (long long)m * lda + kb + kq);
            As[kq + 0][m] = tf32r(va.x);
            As[kq + 1][m] = tf32r(va.y);
            As[kq + 2][m] = tf32r(va.z);
            As[kq + 3][m] = tf32r(va.w);
            float4 vb = *(const float4*)(Bb + (long long)m * ldb + kb + kq);
            Bs[kq + 0][m] = tf32r(vb.x);
            Bs[kq + 1][m] = tf32r(vb.y);
            Bs[kq + 2][m] = tf32r(vb.z);
            Bs[kq + 3][m] = tf32r(vb.w);
        }
        __syncthreads();

#pragma unroll
        for (int ks = 0; ks < 4; ks++) {
            int k0 = ks * 8;
            unsigned a[2][4], b[8][2];
#pragma unroll
            for (int mt = 0; mt < 2; mt++) {
                int mb = wm * 32 + mt * 16;
                a[mt][0] = __float_as_uint(As[k0 + c    ][mb + r    ]);
                a[mt][1] = __float_as_uint(As[k0 + c    ][mb + 8 + r]);
                a[mt][2] = __float_as_uint(As[k0 + 4 + c][mb + r    ]);
                a[mt][3] = __float_as_uint(As[k0 + 4 + c][mb + 8 + r]);
            }
#pragma unroll
            for (int nt = 0; nt < 8; nt++) {
                int nb = wn * 64 + nt * 8;
                b[nt][0] = __float_as_uint(Bs[k0 + c    ][nb + r]);
                b[nt][1] = __float_as_uint(Bs[k0 + 4 + c][nb + r]);
            }
#pragma unroll
            for (int mt = 0; mt < 2; mt++)
#pragma unroll
                for (int nt = 0; nt < 8; nt++)
                    mma_tf32(acc[mt][nt], a[mt], b[nt]);
        }
        __syncthreads();
    }

    // epilogue
#pragma unroll
    for (int mt = 0; mt < 2; mt++) {
        int m0 = bm * BM + wm * 32 + mt * 16 + r;
#pragma unroll
        for (int nt = 0; nt < 8; nt++) {
            int n0 = bn * BN + wn * 64 + nt * 8 + 2 * c;
            float2 v0 = make_float2(acc[mt][nt][0] * scale, acc[mt][nt][1] * scale);
            float2 v1 = make_float2(acc[mt][nt][2] * scale, acc[mt][nt][3] * scale);
            *(float2*)(C + (long long)m0 * ldc + n0)       = v0;
            *(float2*)(C + (long long)(m0 + 8) * ldc + n0) = v1;
        }
    }
}

// ---------------- inv_freq (fp64 once, cast to fp32 to match jnp) ----------------
__global__ void init_invf() {
    int i = threadIdx.x;
    if (i < 64)
        g_invf[i] = (float)exp(-(double)i * (log(10000.0) / 64.0));
}

// ---------------- RMSNorm + RoPE + reorder ----------------
// grid(T, 40): y in [0,32) -> q head; [32,36) -> k head; [36,40) -> v passthrough
// NOTE: positions is int32 on the wire (JAX default config downcasts int64).
__global__ __launch_bounds__(128) void norm_rope(
    const int* __restrict__ positions,
    const float* __restrict__ qw, const float* __restrict__ kw)
{
    int t = blockIdx.x, hh = blockIdx.y, d = threadIdx.x;

    if (hh >= 36) {
        int kvh = hh - 36;
        float v = g_qkv[(long long)t * QKVN + QS + KVS + kvh * HD + d];
        g_vt[((long long)kvh * HD + d) * TT + t] = v;   // [kv][d][t]
        return;
    }

    float x;
    if (hh < 32) x = g_qkv[(long long)t * QKVN + hh * HD + d];
    else         x = g_qkv[(long long)t * QKVN + QS + (hh - 32) * HD + d];

    // block reduce sum of squares (128 threads = 4 warps)
    __shared__ float red[4];
    __shared__ float ybuf[HD];
    float s = x * x;
#pragma unroll
    for (int o = 16; o; o >>= 1) s += __shfl_xor_sync(0xffffffffu, s, o);
    if ((d & 31) == 0) red[d >> 5] = s;
    __syncthreads();
    float tot = red[0] + red[1] + red[2] + red[3];

    const float* w = (hh < 32) ? qw : kw;
    float y = x * rsqrtf(tot * (1.0f / HD) + 1e-6f) * w[d];

    ybuf[d] = y;
    __syncthreads();

    int i = d & 63;
    float pos = (float)positions[t];
    float ang = pos * g_invf[i];          // fp32 multiply, matches jnp rounding
    float cs = cosf(ang), sn = sinf(ang);
    float out;
    if (d < 64) out = y * cs - ybuf[d + 64] * sn;
    else        out = y * cs + ybuf[d - 64] * sn;

    if (hh < 32) g_q[((long long)hh * TT + t) * HD + d] = out;
    else         g_k[((long long)(hh - 32) * TT + t) * HD + d] = out;
}

// ---------------- causal row softmax over g_s, in place ----------------
// one block per (h, q) row; writes P for k<=q, zeros for q<k<limit (PV read window)
__global__ __launch_bounds__(256) void softmax_kernel() {
    __shared__ float smax[8], ssum[8], sbc[2];
    int row = blockIdx.x;
    int h = row >> 11, q = row & (TT - 1);
    float* s = g_s + ((long long)h * TT + q) * TT;
    int n = q + 1;
    int limit = ((q >> 7) + 1) << 7;
    int tid = threadIdx.x;

    float v[8];
    float mx = -FLT_MAX;
#pragma unroll
    for (int j = 0; j < 8; j++) {
        int k = tid + 256 * j;
        v[j] = (k < n) ? s[k] : -FLT_MAX;
        mx = fmaxf(mx, v[j]);
    }
#pragma unroll
    for (int o = 16; o; o >>= 1) mx = fmaxf(mx, __shfl_xor_sync(0xffffffffu, mx, o));
    if ((tid & 31) == 0) smax[tid >> 5] = mx;
    __syncthreads();
    if (tid == 0) {
        float m2 = smax[0];
#pragma unroll
        for (int i = 1; i < 8; i++) m2 = fmaxf(m2, smax[i]);
        sbc[0] = m2;
    }
    __syncthreads();
    mx = sbc[0];

    float e[8];
    float sum = 0.f;
#pragma unroll
    for (int j = 0; j < 8; j++) {
        int k = tid + 256 * j;
        e[j] = (k < n) ? expf(v[j] - mx) : 0.f;
        sum += e[j];
    }
#pragma unroll
    for (int o = 16; o; o >>= 1) sum += __shfl_xor_sync(0xffffffffu, sum, o);
    if ((tid & 31) == 0) ssum[tid >> 5] = sum;
    __syncthreads();
    if (tid == 0) {
        float t2 = 0.f;
#pragma unroll
        for (int i = 0; i < 8; i++) t2 += ssum[i];
        sbc[1] = t2;
    }
    __syncthreads();
    float inv = 1.f / sbc[1];
#pragma unroll
    for (int j = 0; j < 8; j++) {
        int k = tid + 256 * j;
        if (k < limit) s[k] = e[j] * inv;
    }
}

// ---------------- launcher ----------------
extern "C" void kernel_launch(void* const* d_in, const int* in_sizes, int n_in,
                              void* d_out, int out_size)
{
    const int* positions = (const int*)d_in[0];   // int32 (JAX x64 disabled)
    const float* hidden = (const float*)d_in[1];
    const float* w_qkv  = (const float*)d_in[2];
    const float* w_o    = (const float*)d_in[3];
    const float* qw     = (const float*)d_in[4];
    const float* kw     = (const float*)d_in[5];
    float* out = (float*)d_out;

    float *p_qkv, *p_q, *p_k, *p_vt, *p_s, *p_attn;
    cudaGetSymbolAddress((void**)&p_qkv,  g_qkv);
    cudaGetSymbolAddress((void**)&p_q,    g_q);
    cudaGetSymbolAddress((void**)&p_k,    g_k);
    cudaGetSymbolAddress((void**)&p_vt,   g_vt);
    cudaGetSymbolAddress((void**)&p_s,    g_s);
    cudaGetSymbolAddress((void**)&p_attn, g_attn);

    init_invf<<<1, 64>>>();

    // 1) QKV projection: [T,5120] = hidden[T,2048] @ w_qkv[5120,2048]^T
    gemm_tn<<<dim3(QKVN / BN, TT / BM, 1), 256>>>(
        hidden, w_qkv, p_qkv, TT, QKVN, HIDDEN,
        HIDDEN, HIDDEN, QKVN, 0, 0, 0, 0, 1.0f, 0);

    // 2) RMSNorm + RoPE + reorder (q head-major, k head-major, v transposed)
    norm_rope<<<dim3(TT, 40), 128>>>(positions, qw, kw);

    // 3) S = Q K^T * d^-0.5 (batched over 32 heads, triangular skip)
    gemm_tn<<<dim3(TT / BN, TT / BM, NH), 256>>>(
        p_q, p_k, p_s, TT, TT, HD,
        HD, HD, TT,
        (long long)TT * HD, (long long)TT * HD, (long long)TT * TT,
        3, 0.08838834764831845f, 1);

    // 4) causal softmax in place
    softmax_kernel<<<NH * TT, 256>>>();

    // 5) O_h = P_h @ V, via V^T (TN), causal k-limit
    gemm_tn<<<dim3(HD / BN, TT / BM, NH), 256>>>(
        p_s, p_vt, p_attn, TT, HD, TT,
        TT, TT, QS,
        (long long)TT * TT, (long long)HD * TT, (long long)HD,
        3, 1.0f, 2);

    // 6) output projection: out[T,2048] = attn[T,4096] @ w_o[2048,4096]^T
    gemm_tn<<<dim3(HIDDEN / BN, TT / BM, 1), 256>>>(
        p_attn, w_o, out, TT, HIDDEN, QS,
        QS, QS, HIDDEN, 0, 0, 0, 0, 1.0f, 0);
}

// round 4
// speedup vs baseline: 1.6406x; 1.6406x over previous
#include <cuda_runtime.h>
#include <math.h>
#include <float.h>
#include <stdint.h>

#define TT 2048
#define HIDDEN 2048
#define NH 32
#define NKV 4
#define HD 128
#define QS (NH*HD)        // 4096
#define KVS (NKV*HD)      // 512
#define QKVN (QS + 2*KVS) // 5120

// ---------------- scratch (static device globals; no allocs) ----------------
__device__ float g_qkv [(size_t)TT * QKVN];     //  40 MB
__device__ float g_q   [(size_t)NH * TT * HD];  //  32 MB  [h][t][d]
__device__ float g_k   [(size_t)NKV * TT * HD]; //   4 MB  [kv][t][d]
__device__ float g_vt  [(size_t)NKV * HD * TT]; //   4 MB  [kv][d][t] (transposed)
__device__ float g_s   [(size_t)NH * TT * TT];  // 536 MB  [h][q][k]
__device__ float g_attn[(size_t)TT * QS];       //  32 MB  [t][h*128+d]
__device__ float g_invf[64];

// ---------------- helpers ----------------
__device__ __forceinline__ float tf32r(float x) {
    unsigned o;
    asm("cvt.rna.tf32.f32 %0, %1;" : "=r"(o) : "f"(x));
    return __uint_as_float(o);
}

__device__ __forceinline__ void mma_tf32(float* d, const unsigned* a, const unsigned* b) {
    asm volatile(
        "mma.sync.aligned.m16n8k8.row.col.f32.tf32.tf32.f32 "
        "{%0,%1,%2,%3}, {%4,%5,%6,%7}, {%8,%9}, {%0,%1,%2,%3};\n"
        : "+f"(d[0]), "+f"(d[1]), "+f"(d[2]), "+f"(d[3])
        : "r"(a[0]), "r"(a[1]), "r"(a[2]), "r"(a[3]), "r"(b[0]), "r"(b[1]));
}

// ---------------- fragment-major smem layout ----------------
// A: per stage: 8 mtiles x 4 kg tiles, tile = 32 lanes x 16B (a0..a3), stride 528B
//    tile index ta = mt*4 + kg. Stage size = 32*528 = 16896 B.
// B: per stage: 16 ntiles x 4 kg tiles, tile = 32 lanes x 8B (b0,b1), stride 272B
//    tile index tb = nt*4 + kg. Stage size = 64*272 = 17408 B.
#define A_TILE_STRIDE 528
#define B_TILE_STRIDE 272
#define A_STAGE 16896
#define B_STAGE 17408
#define SM_B_OFF (2*A_STAGE)             // 33792
#define SM_TOT   (2*A_STAGE + 2*B_STAGE) // 68608

#define BM 128
#define BN 128
#define BK 32

// ---------------- tf32 TN GEMM: C[M,N] = A[M,K] * B[N,K]^T ----------------
// mode 0: plain; mode 1: triangular skip (bn>bm); mode 2: causal k-limit
// batch z: A += z*sA; B += (z>>bShift)*sB; C += z*sC
__global__ __launch_bounds__(256, 2) void gemm_tn(
    const float* __restrict__ A, const float* __restrict__ B, float* __restrict__ C,
    int K, int lda, int ldb, int ldc,
    long long sA, long long sB, long long sC, int bShift,
    float scale, int mode)
{
    int bm = blockIdx.y, bn = blockIdx.x, z = blockIdx.z;
    if (mode == 1 && bn > bm) return;

    A += (long long)z * sA;
    B += (long long)(z >> bShift) * sB;
    C += (long long)z * sC;

    extern __shared__ char smem[];

    int tid  = threadIdx.x;
    int warp = tid >> 5, lane = tid & 31;
    int wm = warp & 3, wn = warp >> 2;   // 4 x 2 warp grid (m x n)

    // staging constants
    int kq    = (tid & 7) << 2;          // k offset of this thread's float4
    int kg    = (tid & 7) >> 1;          // k-group (8-wide) index
    int khalf = tid & 1;                 // k half within group (c vs c+4)
    int mrow  = tid >> 3;                // base row (0..31), +32*i

    float acc[2][8][4];
#pragma unroll
    for (int i = 0; i < 2; i++)
#pragma unroll
        for (int j = 0; j < 8; j++)
#pragma unroll
            for (int k = 0; k < 4; k++) acc[i][j][k] = 0.f;

    int kmax = (mode == 2) ? min(K, (bm + 1) * BM) : K;
    int nkt = kmax >> 5;

    const float* Ab = A + (long long)bm * BM * lda;
    const float* Bb = B + (long long)bn * BN * ldb;

    float4 ra[4], rbg[4];

    // ---- prologue: load + stage kt = 0 ----
    {
        const float* ap = Ab + kq;
        const float* bp = Bb + kq;
#pragma unroll
        for (int i = 0; i < 4; i++) {
            ra[i]  = *(const float4*)(ap + (long long)(mrow + 32 * i) * lda);
            rbg[i] = *(const float4*)(bp + (long long)(mrow + 32 * i) * ldb);
        }
        char* da = smem;
        char* db = smem + SM_B_OFF;
#pragma unroll
        for (int i = 0; i < 4; i++) {
            int m = mrow + 32 * i;
            int mt = m >> 4, r = m & 7, rb2 = (m >> 3) & 1;
            char* abase = da + (mt * 4 + kg) * A_TILE_STRIDE + (rb2 + 2 * khalf) * 4 + r * 64;
            float av[4] = {ra[i].x, ra[i].y, ra[i].z, ra[i].w};
#pragma unroll
            for (int j = 0; j < 4; j++) *(float*)(abase + j * 16) = tf32r(av[j]);
            int ntl = m >> 3, rn = m & 7;
            char* bbase = db + (ntl * 4 + kg) * B_TILE_STRIDE + khalf * 4 + rn * 32;
            float bv[4] = {rbg[i].x, rbg[i].y, rbg[i].z, rbg[i].w};
#pragma unroll
            for (int j = 0; j < 4; j++) *(float*)(bbase + j * 8) = tf32r(bv[j]);
        }
    }
    __syncthreads();

    for (int kt = 0; kt < nkt; kt++) {
        int stage = kt & 1;

        // prefetch kt+1 (in flight during compute)
        if (kt + 1 < nkt) {
            int kb = (kt + 1) << 5;
            const float* ap = Ab + kb + kq;
            const float* bp = Bb + kb + kq;
#pragma unroll
            for (int i = 0; i < 4; i++) {
                ra[i]  = *(const float4*)(ap + (long long)(mrow + 32 * i) * lda);
                rbg[i] = *(const float4*)(bp + (long long)(mrow + 32 * i) * ldb);
            }
        }

        // ---- compute from stage ----
        const char* sa = smem + stage * A_STAGE;
        const char* sb = smem + SM_B_OFF + stage * B_STAGE;
#pragma unroll
        for (int ks = 0; ks < 4; ks++) {
            uint4 afr[2];
#pragma unroll
            for (int mt = 0; mt < 2; mt++)
                afr[mt] = *(const uint4*)(sa + ((wm * 2 + mt) * 4 + ks) * A_TILE_STRIDE + lane * 16);
#pragma unroll
            for (int h = 0; h < 2; h++) {
                uint2 bfr[4];
#pragma unroll
                for (int nt4 = 0; nt4 < 4; nt4++)
                    bfr[nt4] = *(const uint2*)(sb + ((wn * 8 + h * 4 + nt4) * 4 + ks) * B_TILE_STRIDE + lane * 8);
#pragma unroll
                for (int mt = 0; mt < 2; mt++)
#pragma unroll
                    for (int nt4 = 0; nt4 < 4; nt4++)
                        mma_tf32(acc[mt][h * 4 + nt4], (const unsigned*)&afr[mt], (const unsigned*)&bfr[nt4]);
            }
        }

        // ---- stage kt+1 into the other buffer ----
        if (kt + 1 < nkt) {
            char* da = smem + (stage ^ 1) * A_STAGE;
            char* db = smem + SM_B_OFF + (stage ^ 1) * B_STAGE;
#pragma unroll
            for (int i = 0; i < 4; i++) {
                int m = mrow + 32 * i;
                int mt = m >> 4, r = m & 7, rb2 = (m >> 3) & 1;
                char* abase = da + (mt * 4 + kg) * A_TILE_STRIDE + (rb2 + 2 * khalf) * 4 + r * 64;
                float av[4] = {ra[i].x, ra[i].y, ra[i].z, ra[i].w};
#pragma unroll
                for (int j = 0; j < 4; j++) *(float*)(abase + j * 16) = tf32r(av[j]);
                int ntl = m >> 3, rn = m & 7;
                char* bbase = db + (ntl * 4 + kg) * B_TILE_STRIDE + khalf * 4 + rn * 32;
                float bv[4] = {rbg[i].x, rbg[i].y, rbg[i].z, rbg[i].w};
#pragma unroll
                for (int j = 0; j < 4; j++) *(float*)(bbase + j * 8) = tf32r(bv[j]);
            }
        }
        __syncthreads();
    }

    // ---- epilogue ----
    int c = lane & 3, r = lane >> 2;
#pragma unroll
    for (int mt = 0; mt < 2; mt++) {
        int m0 = bm * BM + wm * 32 + mt * 16 + r;
#pragma unroll
        for (int nt = 0; nt < 8; nt++) {
            int n0 = bn * BN + wn * 64 + nt * 8 + 2 * c;
            float2 v0 = make_float2(acc[mt][nt][0] * scale, acc[mt][nt][1] * scale);
            float2 v1 = make_float2(acc[mt][nt][2] * scale, acc[mt][nt][3] * scale);
            *(float2*)(C + (long long)m0 * ldc + n0)       = v0;
            *(float2*)(C + (long long)(m0 + 8) * ldc + n0) = v1;
        }
    }
}

// ---------------- inv_freq (fp64 once, cast to fp32 to match jnp) ----------------
__global__ void init_invf() {
    int i = threadIdx.x;
    if (i < 64)
        g_invf[i] = (float)exp(-(double)i * (log(10000.0) / 64.0));
}

// ---------------- RMSNorm + RoPE + reorder ----------------
// grid(T, 40): y in [0,32) -> q head; [32,36) -> k head; [36,40) -> v passthrough
// NOTE: positions is int32 on the wire (JAX default config downcasts int64).
__global__ __launch_bounds__(128) void norm_rope(
    const int* __restrict__ positions,
    const float* __restrict__ qw, const float* __restrict__ kw)
{
    int t = blockIdx.x, hh = blockIdx.y, d = threadIdx.x;

    if (hh >= 36) {
        int kvh = hh - 36;
        float v = g_qkv[(long long)t * QKVN + QS + KVS + kvh * HD + d];
        g_vt[((long long)kvh * HD + d) * TT + t] = v;   // [kv][d][t]
        return;
    }

    float x;
    if (hh < 32) x = g_qkv[(long long)t * QKVN + hh * HD + d];
    else         x = g_qkv[(long long)t * QKVN + QS + (hh - 32) * HD + d];

    __shared__ float red[4];
    __shared__ float ybuf[HD];
    float s = x * x;
#pragma unroll
    for (int o = 16; o; o >>= 1) s += __shfl_xor_sync(0xffffffffu, s, o);
    if ((d & 31) == 0) red[d >> 5] = s;
    __syncthreads();
    float tot = red[0] + red[1] + red[2] + red[3];

    const float* w = (hh < 32) ? qw : kw;
    float y = x * rsqrtf(tot * (1.0f / HD) + 1e-6f) * w[d];

    ybuf[d] = y;
    __syncthreads();

    int i = d & 63;
    float pos = (float)positions[t];
    float ang = pos * g_invf[i];
    float cs = cosf(ang), sn = sinf(ang);
    float out;
    if (d < 64) out = y * cs - ybuf[d + 64] * sn;
    else        out = y * cs + ybuf[d - 64] * sn;

    if (hh < 32) g_q[((long long)hh * TT + t) * HD + d] = out;
    else         g_k[((long long)(hh - 32) * TT + t) * HD + d] = out;
}

// ---------------- causal row softmax over g_s, in place ----------------
__global__ __launch_bounds__(256) void softmax_kernel() {
    __shared__ float smax[8], ssum[8], sbc[2];
    int row = blockIdx.x;
    int h = row >> 11, q = row & (TT - 1);
    float* s = g_s + ((long long)h * TT + q) * TT;
    int n = q + 1;
    int limit = ((q >> 7) + 1) << 7;
    int tid = threadIdx.x;

    float v[8];
    float mx = -FLT_MAX;
#pragma unroll
    for (int j = 0; j < 8; j++) {
        int k = tid + 256 * j;
        v[j] = (k < n) ? s[k] : -FLT_MAX;
        mx = fmaxf(mx, v[j]);
    }
#pragma unroll
    for (int o = 16; o; o >>= 1) mx = fmaxf(mx, __shfl_xor_sync(0xffffffffu, mx, o));
    if ((tid & 31) == 0) smax[tid >> 5] = mx;
    __syncthreads();
    if (tid == 0) {
        float m2 = smax[0];
#pragma unroll
        for (int i = 1; i < 8; i++) m2 = fmaxf(m2, smax[i]);
        sbc[0] = m2;
    }
    __syncthreads();
    mx = sbc[0];

    float e[8];
    float sum = 0.f;
#pragma unroll
    for (int j = 0; j < 8; j++) {
        int k = tid + 256 * j;
        e[j] = (k < n) ? expf(v[j] - mx) : 0.f;
        sum += e[j];
    }
#pragma unroll
    for (int o = 16; o; o >>= 1) sum += __shfl_xor_sync(0xffffffffu, sum, o);
    if ((tid & 31) == 0) ssum[tid >> 5] = sum;
    __syncthreads();
    if (tid == 0) {
        float t2 = 0.f;
#pragma unroll
        for (int i = 0; i < 8; i++) t2 += ssum[i];
        sbc[1] = t2;
    }
    __syncthreads();
    float inv = 1.f / sbc[1];
#pragma unroll
    for (int j = 0; j < 8; j++) {
        int k = tid + 256 * j;
        if (k < limit) s[k] = e[j] * inv;
    }
}

// ---------------- launcher ----------------
extern "C" void kernel_launch(void* const* d_in, const int* in_sizes, int n_in,
                              void* d_out, int out_size)
{
    const int* positions = (const int*)d_in[0];   // int32 (JAX x64 disabled)
    const float* hidden = (const float*)d_in[1];
    const float* w_qkv  = (const float*)d_in[2];
    const float* w_o    = (const float*)d_in[3];
    const float* qw     = (const float*)d_in[4];
    const float* kw     = (const float*)d_in[5];
    float* out = (float*)d_out;

    float *p_qkv, *p_q, *p_k, *p_vt, *p_s, *p_attn;
    cudaGetSymbolAddress((void**)&p_qkv,  g_qkv);
    cudaGetSymbolAddress((void**)&p_q,    g_q);
    cudaGetSymbolAddress((void**)&p_k,    g_k);
    cudaGetSymbolAddress((void**)&p_vt,   g_vt);
    cudaGetSymbolAddress((void**)&p_s,    g_s);
    cudaGetSymbolAddress((void**)&p_attn, g_attn);

    cudaFuncSetAttribute(gemm_tn, cudaFuncAttributeMaxDynamicSharedMemorySize, SM_TOT);

    init_invf<<<1, 64>>>();

    // 1) QKV projection: [T,5120] = hidden[T,2048] @ w_qkv[5120,2048]^T
    gemm_tn<<<dim3(QKVN / BN, TT / BM, 1), 256, SM_TOT>>>(
        hidden, w_qkv, p_qkv, HIDDEN,
        HIDDEN, HIDDEN, QKVN, 0, 0, 0, 0, 1.0f, 0);

    // 2) RMSNorm + RoPE + reorder
    norm_rope<<<dim3(TT, 40), 128>>>(positions, qw, kw);

    // 3) S = Q K^T * d^-0.5 (batched over 32 heads, triangular skip)
    gemm_tn<<<dim3(TT / BN, TT / BM, NH), 256, SM_TOT>>>(
        p_q, p_k, p_s, HD,
        HD, HD, TT,
        (long long)TT * HD, (long long)TT * HD, (long long)TT * TT,
        3, 0.08838834764831845f, 1);

    // 4) causal softmax in place
    softmax_kernel<<<NH * TT, 256>>>();

    // 5) O_h = P_h @ V, via V^T (TN), causal k-limit
    gemm_tn<<<dim3(HD / BN, TT / BM, NH), 256, SM_TOT>>>(
        p_s, p_vt, p_attn, TT,
        TT, TT, QS,
        (long long)TT * TT, (long long)HD * TT, (long long)HD,
        3, 1.0f, 2);

    // 6) output projection: out[T,2048] = attn[T,4096] @ w_o[2048,4096]^T
    gemm_tn<<<dim3(HIDDEN / BN, TT / BM, 1), 256, SM_TOT>>>(
        p_attn, w_o, out, QS,
        QS, QS, HIDDEN, 0, 0, 0, 0, 1.0f, 0);
}

// round 5
// speedup vs baseline: 1.9424x; 1.1840x over previous
#include <cuda_runtime.h>
#include <math.h>
#include <float.h>
#include <stdint.h>

#define TT 2048
#define HIDDEN 2048
#define NH 32
#define NKV 4
#define HD 128
#define QS (NH*HD)        // 4096
#define KVS (NKV*HD)      // 512
#define QKVN (QS + 2*KVS) // 5120

// ---------------- scratch (static device globals; no allocs) ----------------
__device__ float g_qkv [(size_t)TT * QKVN];     //  40 MB (raw fp32, scalar-read only)
__device__ float g_q   [(size_t)NH * TT * HD];  //  32 MB  [h][t][d]   (tf32-rounded)
__device__ float g_k   [(size_t)NKV * TT * HD]; //   4 MB  [kv][t][d]  (tf32-rounded)
__device__ float g_vt  [(size_t)NKV * HD * TT]; //   4 MB  [kv][d][t]  (tf32-rounded)
__device__ float g_s   [(size_t)NH * TT * TT];  // 536 MB  [h][q][k]   P=exp (tf32-rounded)
__device__ float g_attn[(size_t)TT * QS];       //  32 MB  [t][h*128+d](tf32-rounded)
__device__ float g_hidt [(size_t)TT * HIDDEN];  //  16 MB  rna(hidden)
__device__ float g_wqkvt[(size_t)QKVN * HIDDEN];//  40 MB  rna(w_qkv)
__device__ float g_wot  [(size_t)HIDDEN * QS];  //  32 MB  rna(w_o)
__device__ float g_invf[64];

// ---------------- helpers ----------------
__device__ __forceinline__ float tf32r(float x) {
    unsigned o;
    asm("cvt.rna.tf32.f32 %0, %1;" : "=r"(o) : "f"(x));
    return __uint_as_float(o);
}
__device__ __forceinline__ uint32_t smem_u32(const void* p) {
    uint32_t a;
    asm("{ .reg .u64 t; cvta.to.shared.u64 t, %1; cvt.u32.u64 %0, t; }" : "=r"(a) : "l"(p));
    return a;
}
__device__ __forceinline__ void cp16(uint32_t dst, const void* src) {
    asm volatile("cp.async.cg.shared.global [%0], [%1], 16;" :: "r"(dst), "l"(src));
}
__device__ __forceinline__ void mma_tf32(float* d, const unsigned* a, const unsigned* b) {
    asm volatile(
        "mma.sync.aligned.m16n8k8.row.col.f32.tf32.tf32.f32 "
        "{%0,%1,%2,%3}, {%4,%5,%6,%7}, {%8,%9}, {%0,%1,%2,%3};\n"
        : "+f"(d[0]), "+f"(d[1]), "+f"(d[2]), "+f"(d[3])
        : "r"(a[0]), "r"(a[1]), "r"(a[2]), "r"(a[3]), "r"(b[0]), "r"(b[1]));
}

// ---------------- smem: 3-stage ring, row-major + chunk-XOR swizzle ----------------
// stage = A tile 128x32 fp32 (row = 128B = 8 chunks of 16B) + B tile same.
// phys addr of (row m, chunk c4) = m*128 + (c4 ^ (m&7))*16
#define STAGES 3
#define TILE_BYTES 16384
#define STAGE_BYTES 32768
#define SM_TOT (STAGES*STAGE_BYTES + 512)   // + rowsum[128]

#define BM 128
#define BN 128
#define BK 32

// ---------------- tf32 TN GEMM: C[M,N] = A[M,K] * B[N,K]^T ----------------
// mode 0: plain (scale mult, no rounding)
// mode 1: S-exp: triangular block skip; epilogue e = mask ? rna(exp(acc*scale)) : 0
// mode 2: PV: k-loop limit (bm+1)*BM; in-loop row-sums of A(=P); epilogue rna(acc/rowsum)
__global__ __launch_bounds__(256, 2) void gemm_tc(
    const float* __restrict__ A, const float* __restrict__ B, float* __restrict__ C,
    int K, int lda, int ldb, int ldc,
    long long sA, long long sB, long long sC, int bShift,
    float scale, int mode)
{
    int bm = blockIdx.y, bn = blockIdx.x, z = blockIdx.z;
    if (mode == 1 && bn > bm) return;

    A += (long long)z * sA;
    B += (long long)(z >> bShift) * sB;
    C += (long long)z * sC;

    extern __shared__ char smem[];
    uint32_t sbase = smem_u32(smem);
    float* srs = (float*)(smem + STAGES * STAGE_BYTES);

    int tid  = threadIdx.x;
    int warp = tid >> 5, lane = tid & 31;
    int wm = warp & 3, wn = warp >> 2;   // 4 x 2 warp grid (m x n)
    int r = lane >> 2, c = lane & 3;

    float acc[2][8][4];
#pragma unroll
    for (int i = 0; i < 2; i++)
#pragma unroll
        for (int j = 0; j < 8; j++)
#pragma unroll
            for (int k = 0; k < 4; k++) acc[i][j][k] = 0.f;

    int kmax = (mode == 2) ? min(K, (bm + 1) * BM) : K;
    int nkt = kmax >> 5;

    const float* Ab = A + (long long)bm * BM * lda;
    const float* Bb = B + (long long)bn * BN * ldb;

    // staging geometry: thread -> row m=tid>>1, chunks cb..cb+3 (cb = (tid&1)*4)
    int sm_ = tid >> 1;
    int scb = (tid & 1) * 4;
    long long arow = (long long)sm_ * lda;
    long long brow = (long long)sm_ * ldb;

    // ---- prologue: issue stages 0..STAGES-2 ----
#pragma unroll
    for (int p = 0; p < STAGES - 1; p++) {
        if (p < nkt) {
            int kb = p << 5;
            uint32_t aD = sbase + p * STAGE_BYTES + sm_ * 128;
            uint32_t bD = aD + TILE_BYTES;
            const float* as = Ab + arow + kb + scb * 4;
            const float* bs = Bb + brow + kb + scb * 4;
#pragma unroll
            for (int j = 0; j < 4; j++) {
                int sw = ((scb + j) ^ (sm_ & 7)) * 16;
                cp16(aD + sw, as + j * 4);
                cp16(bD + sw, bs + j * 4);
            }
        }
        asm volatile("cp.async.commit_group;" ::: "memory");
    }

    float rs = 0.f;

    for (int kt = 0; kt < nkt; kt++) {
        asm volatile("cp.async.wait_group 1;" ::: "memory");
        __syncthreads();

        // issue copy for kt+2 into stage (kt+2)%3 (== stage computed at kt-1)
        if (kt + STAGES - 1 < nkt) {
            int kn = kt + STAGES - 1;
            int kb = kn << 5;
            uint32_t aD = sbase + (kn % STAGES) * STAGE_BYTES + sm_ * 128;
            uint32_t bD = aD + TILE_BYTES;
            const float* as = Ab + arow + kb + scb * 4;
            const float* bs = Bb + brow + kb + scb * 4;
#pragma unroll
            for (int j = 0; j < 4; j++) {
                int sw = ((scb + j) ^ (sm_ & 7)) * 16;
                cp16(aD + sw, as + j * 4);
                cp16(bD + sw, bs + j * 4);
            }
        }
        asm volatile("cp.async.commit_group;" ::: "memory");

        const char* sa  = smem + (kt % STAGES) * STAGE_BYTES;
        const char* sbm = sa + TILE_BYTES;

        // PV: accumulate row sums of P from this A tile (each thread: its own chunks)
        if (mode == 2) {
            const char* base = sa + sm_ * 128;
#pragma unroll
            for (int j = 0; j < 4; j++) {
                int sw = ((scb + j) ^ (sm_ & 7)) * 16;
                float4 v = *(const float4*)(base + sw);
                rs += v.x + v.y + v.z + v.w;
            }
        }

        // ---- compute ----
#pragma unroll
        for (int ks = 0; ks < 4; ks++) {
            int sw0 = ((2 * ks)     ^ r) * 16 + c * 4;
            int sw1 = ((2 * ks + 1) ^ r) * 16 + c * 4;
            unsigned a[2][4];
#pragma unroll
            for (int mt = 0; mt < 2; mt++) {
                const char* pa = sa + (wm * 32 + mt * 16 + r) * 128;
                a[mt][0] = *(const unsigned*)(pa + sw0);
                a[mt][1] = *(const unsigned*)(pa + 8 * 128 + sw0);
                a[mt][2] = *(const unsigned*)(pa + sw1);
                a[mt][3] = *(const unsigned*)(pa + 8 * 128 + sw1);
            }
            unsigned b[8][2];
#pragma unroll
            for (int nt = 0; nt < 8; nt++) {
                const char* pb = sbm + (wn * 64 + nt * 8 + r) * 128;
                b[nt][0] = *(const unsigned*)(pb + sw0);
                b[nt][1] = *(const unsigned*)(pb + sw1);
            }
#pragma unroll
            for (int mt = 0; mt < 2; mt++)
#pragma unroll
                for (int nt = 0; nt < 8; nt++)
                    mma_tf32(acc[mt][nt], a[mt], b[nt]);
        }
    }

    asm volatile("cp.async.wait_group 0;" ::: "memory");

    if (mode == 2) {
        rs += __shfl_xor_sync(0xffffffffu, rs, 1);
        if (!(tid & 1)) srs[sm_] = rs;
    }
    __syncthreads();

    // ---- epilogue ----
#pragma unroll
    for (int mt = 0; mt < 2; mt++) {
        int mloc = wm * 32 + mt * 16 + r;
        int m0 = bm * BM + mloc;
        float inv0 = 1.f, inv1 = 1.f;
        if (mode == 2) { inv0 = 1.f / srs[mloc]; inv1 = 1.f / srs[mloc + 8]; }
#pragma unroll
        for (int nt = 0; nt < 8; nt++) {
            int n0 = bn * BN + wn * 64 + nt * 8 + 2 * c;
            float v00 = acc[mt][nt][0], v01 = acc[mt][nt][1];
            float v10 = acc[mt][nt][2], v11 = acc[mt][nt][3];
            if (mode == 0) {
                v00 *= scale; v01 *= scale; v10 *= scale; v11 *= scale;
            } else if (mode == 1) {
                v00 = (n0     <= m0    ) ? tf32r(expf(v00 * scale)) : 0.f;
                v01 = (n0 + 1 <= m0    ) ? tf32r(expf(v01 * scale)) : 0.f;
                v10 = (n0     <= m0 + 8) ? tf32r(expf(v10 * scale)) : 0.f;
                v11 = (n0 + 1 <= m0 + 8) ? tf32r(expf(v11 * scale)) : 0.f;
            } else {
                v00 = tf32r(v00 * inv0); v01 = tf32r(v01 * inv0);
                v10 = tf32r(v10 * inv1); v11 = tf32r(v11 * inv1);
            }
            *(float2*)(C + (long long)m0 * ldc + n0)       = make_float2(v00, v01);
            *(float2*)(C + (long long)(m0 + 8) * ldc + n0) = make_float2(v10, v11);
        }
    }
}

// ---------------- rna pre-conversion (float4 grid-stride) ----------------
__global__ void rna_conv(const float4* __restrict__ s, float4* __restrict__ d, int n4) {
    int i = blockIdx.x * 256 + threadIdx.x;
    int stride = gridDim.x * 256;
    for (; i < n4; i += stride) {
        float4 v = s[i];
        d[i] = make_float4(tf32r(v.x), tf32r(v.y), tf32r(v.z), tf32r(v.w));
    }
}

// ---------------- inv_freq (fp64 once, cast to fp32 to match jnp) ----------------
__global__ void init_invf() {
    int i = threadIdx.x;
    if (i < 64)
        g_invf[i] = (float)exp(-(double)i * (log(10000.0) / 64.0));
}

// ---------------- RMSNorm + RoPE + reorder (tf32-rounded outputs) ----------------
// grid(T, 40): y in [0,32) -> q head; [32,36) -> k head; [36,40) -> v passthrough
// NOTE: positions is int32 on the wire (JAX default config downcasts int64).
__global__ __launch_bounds__(128) void norm_rope(
    const int* __restrict__ positions,
    const float* __restrict__ qw, const float* __restrict__ kw)
{
    int t = blockIdx.x, hh = blockIdx.y, d = threadIdx.x;

    if (hh >= 36) {
        int kvh = hh - 36;
        float v = g_qkv[(long long)t * QKVN + QS + KVS + kvh * HD + d];
        g_vt[((long long)kvh * HD + d) * TT + t] = tf32r(v);   // [kv][d][t]
        return;
    }

    float x;
    if (hh < 32) x = g_qkv[(long long)t * QKVN + hh * HD + d];
    else         x = g_qkv[(long long)t * QKVN + QS + (hh - 32) * HD + d];

    __shared__ float red[4];
    __shared__ float ybuf[HD];
    float s = x * x;
#pragma unroll
    for (int o = 16; o; o >>= 1) s += __shfl_xor_sync(0xffffffffu, s, o);
    if ((d & 31) == 0) red[d >> 5] = s;
    __syncthreads();
    float tot = red[0] + red[1] + red[2] + red[3];

    const float* w = (hh < 32) ? qw : kw;
    float y = x * rsqrtf(tot * (1.0f / HD) + 1e-6f) * w[d];

    ybuf[d] = y;
    __syncthreads();

    int i = d & 63;
    float pos = (float)positions[t];
    float ang = pos * g_invf[i];
    float cs = cosf(ang), sn = sinf(ang);
    float out;
    if (d < 64) out = y * cs - ybuf[d + 64] * sn;
    else        out = y * cs + ybuf[d - 64] * sn;

    out = tf32r(out);
    if (hh < 32) g_q[((long long)hh * TT + t) * HD + d] = out;
    else         g_k[((long long)(hh - 32) * TT + t) * HD + d] = out;
}

// ---------------- launcher ----------------
extern "C" void kernel_launch(void* const* d_in, const int* in_sizes, int n_in,
                              void* d_out, int out_size)
{
    const int* positions = (const int*)d_in[0];   // int32 (JAX x64 disabled)
    const float* hidden = (const float*)d_in[1];
    const float* w_qkv  = (const float*)d_in[2];
    const float* w_o    = (const float*)d_in[3];
    const float* qw     = (const float*)d_in[4];
    const float* kw     = (const float*)d_in[5];
    float* out = (float*)d_out;

    float *p_qkv, *p_q, *p_k, *p_vt, *p_s, *p_attn, *p_hidt, *p_wqkvt, *p_wot;
    cudaGetSymbolAddress((void**)&p_qkv,   g_qkv);
    cudaGetSymbolAddress((void**)&p_q,     g_q);
    cudaGetSymbolAddress((void**)&p_k,     g_k);
    cudaGetSymbolAddress((void**)&p_vt,    g_vt);
    cudaGetSymbolAddress((void**)&p_s,     g_s);
    cudaGetSymbolAddress((void**)&p_attn,  g_attn);
    cudaGetSymbolAddress((void**)&p_hidt,  g_hidt);
    cudaGetSymbolAddress((void**)&p_wqkvt, g_wqkvt);
    cudaGetSymbolAddress((void**)&p_wot,   g_wot);

    cudaFuncSetAttribute(gemm_tc, cudaFuncAttributeMaxDynamicSharedMemorySize, SM_TOT);

    init_invf<<<1, 64>>>();

    // 0) pre-round the three external GEMM operands to tf32 grid (rna)
    rna_conv<<<1024, 256>>>((const float4*)hidden, (float4*)p_hidt,  TT * HIDDEN / 4);
    rna_conv<<<1024, 256>>>((const float4*)w_qkv,  (float4*)p_wqkvt, QKVN * HIDDEN / 4);
    rna_conv<<<1024, 256>>>((const float4*)w_o,    (float4*)p_wot,   HIDDEN * QS / 4);

    // 1) QKV projection: [T,5120] = hidden[T,2048] @ w_qkv[5120,2048]^T  (raw fp32 out)
    gemm_tc<<<dim3(QKVN / BN, TT / BM, 1), 256, SM_TOT>>>(
        p_hidt, p_wqkvt, p_qkv, HIDDEN,
        HIDDEN, HIDDEN, QKVN, 0, 0, 0, 0, 1.0f, 0);

    // 2) RMSNorm + RoPE + reorder (tf32-rounded q/k/vt)
    norm_rope<<<dim3(TT, 40), 128>>>(positions, qw, kw);

    // 3) P = exp(Q K^T * scale) with causal mask (batched 32 heads, triangular skip)
    gemm_tc<<<dim3(TT / BN, TT / BM, NH), 256, SM_TOT>>>(
        p_q, p_k, p_s, HD,
        HD, HD, TT,
        (long long)TT * HD, (long long)TT * HD, (long long)TT * TT,
        3, 0.08838834764831845f, 1);

    // 4) O_h = (P_h @ V) / rowsum(P_h), via V^T (TN), causal k-limit
    gemm_tc<<<dim3(HD / BN, TT / BM, NH), 256, SM_TOT>>>(
        p_s, p_vt, p_attn, TT,
        TT, TT, QS,
        (long long)TT * TT, (long long)HD * TT, (long long)HD,
        3, 1.0f, 2);

    // 5) output projection: out[T,2048] = attn[T,4096] @ w_o[2048,4096]^T (exact fp32 out)
    gemm_tc<<<dim3(HIDDEN / BN, TT / BM, 1), 256, SM_TOT>>>(
        p_attn, p_wot, out, QS,
        QS, QS, HIDDEN, 0, 0, 0, 0, 1.0f, 0);
}

// round 6
// speedup vs baseline: 3.3079x; 1.7030x over previous
#include <cuda_runtime.h>
#include <cuda_fp16.h>
#include <math.h>
#include <float.h>
#include <stdint.h>

#define TT 2048
#define HIDDEN 2048
#define NH 32
#define NKV 4
#define HD 128
#define QS (NH*HD)        // 4096
#define KVS (NKV*HD)      // 512
#define QKVN (QS + 2*KVS) // 5120

// ---------------- scratch (static device globals; no allocs) ----------------
__device__ float  g_qkv [(size_t)TT * QKVN];      //  40 MB fp32 (norm input)
__device__ __half g_q   [(size_t)NH * TT * HD];   //  16 MB [h][t][d]
__device__ __half g_k   [(size_t)NKV * TT * HD];  //   2 MB [kv][t][d]
__device__ __half g_vt  [(size_t)NKV * HD * TT];  //   2 MB [kv][d][t]
__device__ __half g_s   [(size_t)NH * TT * TT];   // 268 MB [h][q][k]  P'=exp(s-4)
__device__ __half g_attn[(size_t)TT * QS];        //  16 MB [t][h*128+d]
__device__ __half g_hidh [(size_t)TT * HIDDEN];   //   8 MB fp16(hidden)
__device__ __half g_wqkvh[(size_t)QKVN * HIDDEN]; //  20 MB fp16(w_qkv)
__device__ __half g_woh  [(size_t)HIDDEN * QS];   //  16 MB fp16(w_o)
__device__ float  g_invf[64];

// ---------------- helpers ----------------
__device__ __forceinline__ uint32_t smem_u32(const void* p) {
    uint32_t a;
    asm("{ .reg .u64 t; cvta.to.shared.u64 t, %1; cvt.u32.u64 %0, t; }" : "=r"(a) : "l"(p));
    return a;
}
__device__ __forceinline__ void cp16(uint32_t dst, const void* src) {
    asm volatile("cp.async.cg.shared.global [%0], [%1], 16;" :: "r"(dst), "l"(src));
}
__device__ __forceinline__ void mma_f16(float* d, const unsigned* a, const unsigned* b) {
    asm volatile(
        "mma.sync.aligned.m16n8k16.row.col.f32.f16.f16.f32 "
        "{%0,%1,%2,%3}, {%4,%5,%6,%7}, {%8,%9}, {%0,%1,%2,%3};\n"
        : "+f"(d[0]), "+f"(d[1]), "+f"(d[2]), "+f"(d[3])
        : "r"(a[0]), "r"(a[1]), "r"(a[2]), "r"(a[3]), "r"(b[0]), "r"(b[1]));
}

// ---------------- smem: 3-stage ring, 128B rows + chunk-XOR swizzle ----------------
// tile = 128 rows x 64 halves (128B row = 8 chunks of 16B); stage = A tile + B tile
#define STAGES 3
#define TILE_BYTES 16384
#define STAGE_BYTES 32768
#define SM_TOT (STAGES*STAGE_BYTES + 512)

#define BM 128
#define BN 128
#define BK 64
#define EXP_SHIFT 4.0f

// ---------------- fp16 TN GEMM: C[M,N] = A[M,K] * B[N,K]^T, fp32 accum ----------------
// mode 0: plain fp32 out (x scale)
// mode 1: triangular block skip; epilogue P' = mask ? min(exp(acc*scale-4),6e4) : 0 (half out)
// mode 2: k-limit (bm+1)*128; in-loop row-sums of A(=P'); epilogue half(acc/rowsum)
__global__ __launch_bounds__(256, 2) void gemm_h(
    const __half* __restrict__ A, const __half* __restrict__ B, void* __restrict__ Cv,
    int K, int lda, int ldb, int ldc,
    long long sA, long long sB, long long sC, int bShift,
    float scale, int mode)
{
    int bm = blockIdx.y, bn = blockIdx.x, z = blockIdx.z;
    if (mode == 1 && bn > bm) return;

    A += (long long)z * sA;
    B += (long long)(z >> bShift) * sB;
    long long coff = (long long)z * sC;

    extern __shared__ char smem[];
    uint32_t sbase = smem_u32(smem);
    float* srs = (float*)(smem + STAGES * STAGE_BYTES);

    int tid  = threadIdx.x;
    int warp = tid >> 5, lane = tid & 31;
    int wm = warp & 3, wn = warp >> 2;   // 4 x 2 warp grid (m x n)
    int r = lane >> 2, c = lane & 3;

    float acc[2][8][4];
#pragma unroll
    for (int i = 0; i < 2; i++)
#pragma unroll
        for (int j = 0; j < 8; j++)
#pragma unroll
            for (int k = 0; k < 4; k++) acc[i][j][k] = 0.f;

    int kmax = (mode == 2) ? min(K, (bm + 1) * BM) : K;
    int nkt = kmax >> 6;

    const __half* Ab = A + (long long)bm * BM * lda;
    const __half* Bb = B + (long long)bn * BN * ldb;

    // staging: thread -> row sm_=tid>>1, chunks scb..scb+3 (16B = 8 halves each)
    int sm_ = tid >> 1;
    int scb = (tid & 1) * 4;
    long long arow = (long long)sm_ * lda;
    long long brow = (long long)sm_ * ldb;

    // ---- prologue: issue stages 0..1 ----
#pragma unroll
    for (int p = 0; p < STAGES - 1; p++) {
        if (p < nkt) {
            int kb = p << 6;
            uint32_t aD = sbase + p * STAGE_BYTES + sm_ * 128;
            uint32_t bD = aD + TILE_BYTES;
            const __half* as = Ab + arow + kb + scb * 8;
            const __half* bs = Bb + brow + kb + scb * 8;
#pragma unroll
            for (int j = 0; j < 4; j++) {
                int sw = ((scb + j) ^ (sm_ & 7)) * 16;
                cp16(aD + sw, as + j * 8);
                cp16(bD + sw, bs + j * 8);
            }
        }
        asm volatile("cp.async.commit_group;" ::: "memory");
    }

    float rs = 0.f;

    for (int kt = 0; kt < nkt; kt++) {
        asm volatile("cp.async.wait_group 1;" ::: "memory");
        __syncthreads();

        if (kt + STAGES - 1 < nkt) {
            int kn = kt + STAGES - 1;
            int kb = kn << 6;
            uint32_t aD = sbase + (kn % STAGES) * STAGE_BYTES + sm_ * 128;
            uint32_t bD = aD + TILE_BYTES;
            const __half* as = Ab + arow + kb + scb * 8;
            const __half* bs = Bb + brow + kb + scb * 8;
#pragma unroll
            for (int j = 0; j < 4; j++) {
                int sw = ((scb + j) ^ (sm_ & 7)) * 16;
                cp16(aD + sw, as + j * 8);
                cp16(bD + sw, bs + j * 8);
            }
        }
        asm volatile("cp.async.commit_group;" ::: "memory");

        const char* sa  = smem + (kt % STAGES) * STAGE_BYTES;
        const char* sbm = sa + TILE_BYTES;

        // PV: row sums of P' tile (this thread's staged chunks)
        if (mode == 2) {
            const char* base = sa + sm_ * 128;
#pragma unroll
            for (int j = 0; j < 4; j++) {
                int sw = ((scb + j) ^ (sm_ & 7)) * 16;
                const __half2* hp = (const __half2*)(base + sw);
#pragma unroll
                for (int q2 = 0; q2 < 4; q2++) {
                    float2 t = __half22float2(hp[q2]);
                    rs += t.x + t.y;
                }
            }
        }

        // ---- compute: 4 x k16 ----
#pragma unroll
        for (int ks = 0; ks < 4; ks++) {
            int sw0 = ((2 * ks)     ^ r) * 16 + c * 4;
            int sw1 = ((2 * ks + 1) ^ r) * 16 + c * 4;
            unsigned a[2][4];
#pragma unroll
            for (int mt = 0; mt < 2; mt++) {
                const char* pa = sa + (wm * 32 + mt * 16 + r) * 128;
                a[mt][0] = *(const unsigned*)(pa + sw0);
                a[mt][1] = *(const unsigned*)(pa + 8 * 128 + sw0);
                a[mt][2] = *(const unsigned*)(pa + sw1);
                a[mt][3] = *(const unsigned*)(pa + 8 * 128 + sw1);
            }
            unsigned b[8][2];
#pragma unroll
            for (int nt = 0; nt < 8; nt++) {
                const char* pb = sbm + (wn * 64 + nt * 8 + r) * 128;
                b[nt][0] = *(const unsigned*)(pb + sw0);
                b[nt][1] = *(const unsigned*)(pb + sw1);
            }
#pragma unroll
            for (int mt = 0; mt < 2; mt++)
#pragma unroll
                for (int nt = 0; nt < 8; nt++)
                    mma_f16(acc[mt][nt], a[mt], b[nt]);
        }
    }

    asm volatile("cp.async.wait_group 0;" ::: "memory");

    if (mode == 2) {
        rs += __shfl_xor_sync(0xffffffffu, rs, 1);
        if (!(tid & 1)) srs[sm_] = rs;
    }
    __syncthreads();

    // ---- epilogue ----
#pragma unroll
    for (int mt = 0; mt < 2; mt++) {
        int mloc = wm * 32 + mt * 16 + r;
        int m0 = bm * BM + mloc;
        float inv0 = 1.f, inv1 = 1.f;
        if (mode == 2) { inv0 = 1.f / srs[mloc]; inv1 = 1.f / srs[mloc + 8]; }
#pragma unroll
        for (int nt = 0; nt < 8; nt++) {
            int n0 = bn * BN + wn * 64 + nt * 8 + 2 * c;
            float v00 = acc[mt][nt][0], v01 = acc[mt][nt][1];
            float v10 = acc[mt][nt][2], v11 = acc[mt][nt][3];
            if (mode == 0) {
                float* C = (float*)Cv + coff;
                v00 *= scale; v01 *= scale; v10 *= scale; v11 *= scale;
                *(float2*)(C + (long long)m0 * ldc + n0)       = make_float2(v00, v01);
                *(float2*)(C + (long long)(m0 + 8) * ldc + n0) = make_float2(v10, v11);
            } else if (mode == 1) {
                __half* C = (__half*)Cv + coff;
                v00 = (n0     <= m0    ) ? fminf(expf(v00 * scale - EXP_SHIFT), 60000.f) : 0.f;
                v01 = (n0 + 1 <= m0    ) ? fminf(expf(v01 * scale - EXP_SHIFT), 60000.f) : 0.f;
                v10 = (n0     <= m0 + 8) ? fminf(expf(v10 * scale - EXP_SHIFT), 60000.f) : 0.f;
                v11 = (n0 + 1 <= m0 + 8) ? fminf(expf(v11 * scale - EXP_SHIFT), 60000.f) : 0.f;
                *(__half2*)(C + (long long)m0 * ldc + n0)       = __floats2half2_rn(v00, v01);
                *(__half2*)(C + (long long)(m0 + 8) * ldc + n0) = __floats2half2_rn(v10, v11);
            } else {
                __half* C = (__half*)Cv + coff;
                *(__half2*)(C + (long long)m0 * ldc + n0)       = __floats2half2_rn(v00 * inv0, v01 * inv0);
                *(__half2*)(C + (long long)(m0 + 8) * ldc + n0) = __floats2half2_rn(v10 * inv1, v11 * inv1);
            }
        }
    }
}

// ---------------- fp32 -> fp16 conversion (float4 -> 2x half2) ----------------
__global__ void h_conv(const float4* __restrict__ s, uint2* __restrict__ d, int n4) {
    int i = blockIdx.x * 256 + threadIdx.x;
    int stride = gridDim.x * 256;
    for (; i < n4; i += stride) {
        float4 v = s[i];
        __half2 lo = __floats2half2_rn(v.x, v.y);
        __half2 hi = __floats2half2_rn(v.z, v.w);
        uint2 o;
        o.x = *(unsigned*)&lo;
        o.y = *(unsigned*)&hi;
        d[i] = o;
    }
}

// ---------------- inv_freq (fp64 once, cast to fp32 to match jnp) ----------------
__global__ void init_invf() {
    int i = threadIdx.x;
    if (i < 64)
        g_invf[i] = (float)exp(-(double)i * (log(10000.0) / 64.0));
}

// ---------------- RMSNorm + RoPE + reorder (fp16 outputs) ----------------
// grid(T, 40): y in [0,32) -> q head; [32,36) -> k head; [36,40) -> v passthrough
// NOTE: positions is int32 on the wire (JAX default config downcasts int64).
__global__ __launch_bounds__(128) void norm_rope(
    const int* __restrict__ positions,
    const float* __restrict__ qw, const float* __restrict__ kw)
{
    int t = blockIdx.x, hh = blockIdx.y, d = threadIdx.x;

    if (hh >= 36) {
        int kvh = hh - 36;
        float v = g_qkv[(long long)t * QKVN + QS + KVS + kvh * HD + d];
        g_vt[((long long)kvh * HD + d) * TT + t] = __float2half_rn(v);   // [kv][d][t]
        return;
    }

    float x;
    if (hh < 32) x = g_qkv[(long long)t * QKVN + hh * HD + d];
    else         x = g_qkv[(long long)t * QKVN + QS + (hh - 32) * HD + d];

    __shared__ float red[4];
    __shared__ float ybuf[HD];
    float s = x * x;
#pragma unroll
    for (int o = 16; o; o >>= 1) s += __shfl_xor_sync(0xffffffffu, s, o);
    if ((d & 31) == 0) red[d >> 5] = s;
    __syncthreads();
    float tot = red[0] + red[1] + red[2] + red[3];

    const float* w = (hh < 32) ? qw : kw;
    float y = x * rsqrtf(tot * (1.0f / HD) + 1e-6f) * w[d];

    ybuf[d] = y;
    __syncthreads();

    int i = d & 63;
    float pos = (float)positions[t];
    float ang = pos * g_invf[i];
    float cs = cosf(ang), sn = sinf(ang);
    float out;
    if (d < 64) out = y * cs - ybuf[d + 64] * sn;
    else        out = y * cs + ybuf[d - 64] * sn;

    __half oh = __float2half_rn(out);
    if (hh < 32) g_q[((long long)hh * TT + t) * HD + d] = oh;
    else         g_k[((long long)(hh - 32) * TT + t) * HD + d] = oh;
}

// ---------------- launcher ----------------
extern "C" void kernel_launch(void* const* d_in, const int* in_sizes, int n_in,
                              void* d_out, int out_size)
{
    const int* positions = (const int*)d_in[0];   // int32 (JAX x64 disabled)
    const float* hidden = (const float*)d_in[1];
    const float* w_qkv  = (const float*)d_in[2];
    const float* w_o    = (const float*)d_in[3];
    const float* qw     = (const float*)d_in[4];
    const float* kw     = (const float*)d_in[5];
    float* out = (float*)d_out;

    float *p_qkv;
    __half *p_q, *p_k, *p_vt, *p_s, *p_attn, *p_hidh, *p_wqkvh, *p_woh;
    cudaGetSymbolAddress((void**)&p_qkv,   g_qkv);
    cudaGetSymbolAddress((void**)&p_q,     g_q);
    cudaGetSymbolAddress((void**)&p_k,     g_k);
    cudaGetSymbolAddress((void**)&p_vt,    g_vt);
    cudaGetSymbolAddress((void**)&p_s,     g_s);
    cudaGetSymbolAddress((void**)&p_attn,  g_attn);
    cudaGetSymbolAddress((void**)&p_hidh,  g_hidh);
    cudaGetSymbolAddress((void**)&p_wqkvh, g_wqkvh);
    cudaGetSymbolAddress((void**)&p_woh,   g_woh);

    cudaFuncSetAttribute(gemm_h, cudaFuncAttributeMaxDynamicSharedMemorySize, SM_TOT);

    init_invf<<<1, 64>>>();

    // 0) fp16 conversions of external GEMM operands
    h_conv<<<1024, 256>>>((const float4*)hidden, (uint2*)p_hidh,  TT * HIDDEN / 4);
    h_conv<<<1024, 256>>>((const float4*)w_qkv,  (uint2*)p_wqkvh, QKVN * HIDDEN / 4);
    h_conv<<<1024, 256>>>((const float4*)w_o,    (uint2*)p_woh,   HIDDEN * QS / 4);

    // 1) QKV projection: [T,5120] = hidden @ w_qkv^T  (fp32 out)
    gemm_h<<<dim3(QKVN / BN, TT / BM, 1), 256, SM_TOT>>>(
        p_hidh, p_wqkvh, p_qkv, HIDDEN,
        HIDDEN, HIDDEN, QKVN, 0, 0, 0, 0, 1.0f, 0);

    // 2) RMSNorm + RoPE + reorder (fp16 q/k/vt)
    norm_rope<<<dim3(TT, 40), 128>>>(positions, qw, kw);

    // 3) P' = exp(Q K^T * scale - 4) with causal mask (batched 32 heads, triangular skip)
    gemm_h<<<dim3(TT / BN, TT / BM, NH), 256, SM_TOT>>>(
        p_q, p_k, p_s, HD,
        HD, HD, TT,
        (long long)TT * HD, (long long)TT * HD, (long long)TT * TT,
        3, 0.08838834764831845f, 1);

    // 4) O_h = (P' @ V) / rowsum(P'), via V^T (TN), causal k-limit (fp16 out)
    gemm_h<<<dim3(HD / BN, TT / BM, NH), 256, SM_TOT>>>(
        p_s, p_vt, p_attn, TT,
        TT, TT, QS,
        (long long)TT * TT, (long long)HD * TT, (long long)HD,
        3, 1.0f, 2);

    // 5) output projection: out[T,2048] = attn @ w_o^T (fp32 out)
    gemm_h<<<dim3(HIDDEN / BN, TT / BM, 1), 256, SM_TOT>>>(
        p_attn, p_woh, out, QS,
        QS, QS, HIDDEN, 0, 0, 0, 0, 1.0f, 0);
}

// round 7
// speedup vs baseline: 3.9013x; 1.1794x over previous
#include <cuda_runtime.h>
#include <cuda_fp16.h>
#include <math.h>
#include <float.h>
#include <stdint.h>

#define TT 2048
#define HIDDEN 2048
#define NH 32
#define NKV 4
#define HD 128
#define QS (NH*HD)        // 4096
#define KVS (NKV*HD)      // 512
#define QKVN (QS + 2*KVS) // 5120

// ---------------- scratch (static device globals; no allocs) ----------------
__device__ float  g_qkv [(size_t)TT * QKVN];      //  40 MB fp32 (norm input)
__device__ __half g_q   [(size_t)NH * TT * HD];   //  16 MB [h][t][d]  (pre-scaled by d^-1/2)
__device__ __half g_k   [(size_t)NKV * TT * HD];  //   2 MB [kv][t][d]
__device__ __half g_vt  [(size_t)NKV * HD * TT];  //   2 MB [kv][d][t]
__device__ __half g_attn[(size_t)TT * QS];        //  16 MB [t][h*128+d]
__device__ __half g_hidh [(size_t)TT * HIDDEN];   //   8 MB fp16(hidden)
__device__ __half g_wqkvh[(size_t)QKVN * HIDDEN]; //  20 MB fp16(w_qkv)
__device__ __half g_woh  [(size_t)HIDDEN * QS];   //  16 MB fp16(w_o)
__device__ float  g_invf[64];

#define ATT_SCALE 0.08838834764831845f
#define EXP_SHIFT 4.0f

// ---------------- helpers ----------------
__device__ __forceinline__ uint32_t smem_u32(const void* p) {
    uint32_t a;
    asm("{ .reg .u64 t; cvta.to.shared.u64 t, %1; cvt.u32.u64 %0, t; }" : "=r"(a) : "l"(p));
    return a;
}
__device__ __forceinline__ void cp16(uint32_t dst, const void* src) {
    asm volatile("cp.async.cg.shared.global [%0], [%1], 16;" :: "r"(dst), "l"(src));
}
__device__ __forceinline__ void mma_f16(float* d, const unsigned* a, const unsigned* b) {
    asm volatile(
        "mma.sync.aligned.m16n8k16.row.col.f32.f16.f16.f32 "
        "{%0,%1,%2,%3}, {%4,%5,%6,%7}, {%8,%9}, {%0,%1,%2,%3};\n"
        : "+f"(d[0]), "+f"(d[1]), "+f"(d[2]), "+f"(d[3])
        : "r"(a[0]), "r"(a[1]), "r"(a[2]), "r"(a[3]), "r"(b[0]), "r"(b[1]));
}

// ================= dense fp16 TN GEMM (QKV + O-proj), 3-stage cp.async =================
#define STAGES 3
#define TILE_BYTES 16384
#define STAGE_BYTES 32768
#define SM_TOT (STAGES*STAGE_BYTES + 512)
#define BM 128
#define BN 128

__global__ __launch_bounds__(256, 2) void gemm_h(
    const __half* __restrict__ A, const __half* __restrict__ B, float* __restrict__ C,
    int K, int lda, int ldb, int ldc, float scale)
{
    int bm = blockIdx.y, bn = blockIdx.x;

    extern __shared__ char smem[];
    uint32_t sbase = smem_u32(smem);

    int tid  = threadIdx.x;
    int warp = tid >> 5, lane = tid & 31;
    int wm = warp & 3, wn = warp >> 2;
    int r = lane >> 2, c = lane & 3;

    float acc[2][8][4];
#pragma unroll
    for (int i = 0; i < 2; i++)
#pragma unroll
        for (int j = 0; j < 8; j++)
#pragma unroll
            for (int k = 0; k < 4; k++) acc[i][j][k] = 0.f;

    int nkt = K >> 6;
    const __half* Ab = A + (long long)bm * BM * lda;
    const __half* Bb = B + (long long)bn * BN * ldb;

    int sm_ = tid >> 1;
    int scb = (tid & 1) * 4;
    long long arow = (long long)sm_ * lda;
    long long brow = (long long)sm_ * ldb;

#pragma unroll
    for (int p = 0; p < STAGES - 1; p++) {
        if (p < nkt) {
            int kb = p << 6;
            uint32_t aD = sbase + p * STAGE_BYTES + sm_ * 128;
            uint32_t bD = aD + TILE_BYTES;
            const __half* as = Ab + arow + kb + scb * 8;
            const __half* bs = Bb + brow + kb + scb * 8;
#pragma unroll
            for (int j = 0; j < 4; j++) {
                int sw = ((scb + j) ^ (sm_ & 7)) * 16;
                cp16(aD + sw, as + j * 8);
                cp16(bD + sw, bs + j * 8);
            }
        }
        asm volatile("cp.async.commit_group;" ::: "memory");
    }

    for (int kt = 0; kt < nkt; kt++) {
        asm volatile("cp.async.wait_group 1;" ::: "memory");
        __syncthreads();

        if (kt + STAGES - 1 < nkt) {
            int kn = kt + STAGES - 1;
            int kb = kn << 6;
            uint32_t aD = sbase + (kn % STAGES) * STAGE_BYTES + sm_ * 128;
            uint32_t bD = aD + TILE_BYTES;
            const __half* as = Ab + arow + kb + scb * 8;
            const __half* bs = Bb + brow + kb + scb * 8;
#pragma unroll
            for (int j = 0; j < 4; j++) {
                int sw = ((scb + j) ^ (sm_ & 7)) * 16;
                cp16(aD + sw, as + j * 8);
                cp16(bD + sw, bs + j * 8);
            }
        }
        asm volatile("cp.async.commit_group;" ::: "memory");

        const char* sa  = smem + (kt % STAGES) * STAGE_BYTES;
        const char* sbm = sa + TILE_BYTES;

#pragma unroll
        for (int ks = 0; ks < 4; ks++) {
            int sw0 = ((2 * ks)     ^ r) * 16 + c * 4;
            int sw1 = ((2 * ks + 1) ^ r) * 16 + c * 4;
            unsigned a[2][4];
#pragma unroll
            for (int mt = 0; mt < 2; mt++) {
                const char* pa = sa + (wm * 32 + mt * 16 + r) * 128;
                a[mt][0] = *(const unsigned*)(pa + sw0);
                a[mt][1] = *(const unsigned*)(pa + 8 * 128 + sw0);
                a[mt][2] = *(const unsigned*)(pa + sw1);
                a[mt][3] = *(const unsigned*)(pa + 8 * 128 + sw1);
            }
            unsigned b[8][2];
#pragma unroll
            for (int nt = 0; nt < 8; nt++) {
                const char* pb = sbm + (wn * 64 + nt * 8 + r) * 128;
                b[nt][0] = *(const unsigned*)(pb + sw0);
                b[nt][1] = *(const unsigned*)(pb + sw1);
            }
#pragma unroll
            for (int mt = 0; mt < 2; mt++)
#pragma unroll
                for (int nt = 0; nt < 8; nt++)
                    mma_f16(acc[mt][nt], a[mt], b[nt]);
        }
    }

    asm volatile("cp.async.wait_group 0;" ::: "memory");

#pragma unroll
    for (int mt = 0; mt < 2; mt++) {
        int m0 = bm * BM + wm * 32 + mt * 16 + r;
#pragma unroll
        for (int nt = 0; nt < 8; nt++) {
            int n0 = bn * BN + wn * 64 + nt * 8 + 2 * c;
            *(float2*)(C + (long long)m0 * ldc + n0) =
                make_float2(acc[mt][nt][0] * scale, acc[mt][nt][1] * scale);
            *(float2*)(C + (long long)(m0 + 8) * ldc + n0) =
                make_float2(acc[mt][nt][2] * scale, acc[mt][nt][3] * scale);
        }
    }
}

// ================= fused flash attention =================
// block = (head h, q-block bm). 512 threads, 16 warps: wm=w&7 (m16 rows), wn=w>>3 (kv/d slice).
// smem: Q 32KB | K 2x32KB | V 2x32KB | rowsum 1KB.  O-reduction reuses K area (64KB).
#define FSM_Q 0
#define FSM_K 32768
#define FSM_V (32768 + 65536)
#define FSM_L (FSM_V + 65536)
#define FSM_TOT (FSM_L + 1024 + 128)

__device__ __forceinline__ void flash_load_tile128(
    uint32_t sdst, const __half* src, int ld, int tid)
{
    // 128 rows x 128 halves -> 2 ktiles of [128 rows x 64 halves], chunk-XOR swizzle
#pragma unroll
    for (int i = 0; i < 4; i++) {
        int li = tid + 512 * i;
        int row = li >> 4, cc = li & 15;
        uint32_t dst = sdst + (cc >> 3) * 16384 + row * 128 + (((cc & 7) ^ (row & 7)) * 16);
        cp16(dst, src + (long long)row * ld + cc * 8);
    }
}

__global__ __launch_bounds__(512, 1) void flash_kernel()
{
    int b = blockIdx.x;
    int bm = 15 - (b >> 5);     // heavy blocks first
    int h  = b & 31;
    int kvh = h >> 3;

    extern __shared__ char sm[];
    uint32_t sbase = smem_u32(sm);
    float* lsum = (float*)(sm + FSM_L);

    int tid = threadIdx.x;
    int w = tid >> 5, lane = tid & 31;
    int wm = w & 7, wn = w >> 3;
    int r = lane >> 2, c = lane & 3;

    const __half* qsrc = g_q + ((size_t)h * TT + (size_t)bm * 128) * HD;
    const __half* ksrc = g_k + (size_t)kvh * TT * HD;
    const __half* vsrc = g_vt + (size_t)kvh * HD * TT;

    // prologue: Q + K/V stage 0
    flash_load_tile128(sbase + FSM_Q, qsrc, HD, tid);
    flash_load_tile128(sbase + FSM_K, ksrc, HD, tid);
    {
        // V^T rows = d (ld = TT), columns = kv block 0
#pragma unroll
        for (int i = 0; i < 4; i++) {
            int li = tid + 512 * i;
            int row = li >> 4, cc = li & 15;
            uint32_t dst = sbase + FSM_V + (cc >> 3) * 16384 + row * 128 + (((cc & 7) ^ (row & 7)) * 16);
            cp16(dst, vsrc + (size_t)row * TT + cc * 8);
        }
    }
    asm volatile("cp.async.commit_group;" ::: "memory");

    float acc_o[16][4];
#pragma unroll
    for (int i = 0; i < 16; i++)
#pragma unroll
        for (int k = 0; k < 4; k++) acc_o[i][k] = 0.f;
    float l0 = 0.f, l1 = 0.f;

    int mrow0 = wm * 16 + r;

    for (int j = 0; j <= bm; j++) {
        int st = j & 1;
        asm volatile("cp.async.wait_group 0;" ::: "memory");
        __syncthreads();

        if (j < bm) {   // prefetch j+1 into the other stage
            int jn = j + 1;
            flash_load_tile128(sbase + FSM_K + (st ^ 1) * 32768,
                               ksrc + (size_t)jn * 128 * HD, HD, tid);
#pragma unroll
            for (int i = 0; i < 4; i++) {
                int li = tid + 512 * i;
                int row = li >> 4, cc = li & 15;
                uint32_t dst = sbase + FSM_V + (st ^ 1) * 32768 + (cc >> 3) * 16384
                             + row * 128 + (((cc & 7) ^ (row & 7)) * 16);
                cp16(dst, vsrc + (size_t)row * TT + jn * 128 + cc * 8);
            }
        }
        asm volatile("cp.async.commit_group;" ::: "memory");

        // ---- S = Q @ K^T (Q pre-scaled) ----
        float acc_s[8][4];
#pragma unroll
        for (int i = 0; i < 8; i++)
#pragma unroll
            for (int k = 0; k < 4; k++) acc_s[i][k] = 0.f;

        const char* sq = sm + FSM_Q;
        const char* sk = sm + FSM_K + st * 32768;
#pragma unroll
        for (int kt = 0; kt < 2; kt++) {
#pragma unroll
            for (int ks = 0; ks < 4; ks++) {
                int sw0 = ((2 * ks)     ^ r) * 16 + c * 4;
                int sw1 = ((2 * ks + 1) ^ r) * 16 + c * 4;
                const char* pa = sq + kt * 16384 + (wm * 16 + r) * 128;
                unsigned a[4];
                a[0] = *(const unsigned*)(pa + sw0);
                a[1] = *(const unsigned*)(pa + 8 * 128 + sw0);
                a[2] = *(const unsigned*)(pa + sw1);
                a[3] = *(const unsigned*)(pa + 8 * 128 + sw1);
#pragma unroll
                for (int nt = 0; nt < 8; nt++) {
                    const char* pb = sk + kt * 16384 + (wn * 64 + nt * 8 + r) * 128;
                    unsigned bb[2];
                    bb[0] = *(const unsigned*)(pb + sw0);
                    bb[1] = *(const unsigned*)(pb + sw1);
                    mma_f16(acc_s[nt], a, bb);
                }
            }
        }

        // ---- exp + causal mask + pack to fp16 A-frags + rowsums ----
        unsigned p[16];
        bool diag = (j == bm);
#pragma unroll
        for (int nt = 0; nt < 8; nt++) {
            int n0 = wn * 64 + nt * 8 + 2 * c;
            float v0 = __expf(acc_s[nt][0] - EXP_SHIFT);
            float v1 = __expf(acc_s[nt][1] - EXP_SHIFT);
            float v2 = __expf(acc_s[nt][2] - EXP_SHIFT);
            float v3 = __expf(acc_s[nt][3] - EXP_SHIFT);
            if (diag) {
                if (n0     > mrow0)     v0 = 0.f;
                if (n0 + 1 > mrow0)     v1 = 0.f;
                if (n0     > mrow0 + 8) v2 = 0.f;
                if (n0 + 1 > mrow0 + 8) v3 = 0.f;
            }
            l0 += v0 + v1;
            l1 += v2 + v3;
            __half2 h01 = __floats2half2_rn(v0, v1);
            __half2 h23 = __floats2half2_rn(v2, v3);
            p[2 * nt]     = *(unsigned*)&h01;
            p[2 * nt + 1] = *(unsigned*)&h23;
        }

        // ---- O += P @ V (each warp over its 64-kv slice, full d=128) ----
        const char* sv = sm + FSM_V + st * 32768 + wn * 16384;
#pragma unroll
        for (int ks = 0; ks < 4; ks++) {
            int sw0 = ((2 * ks)     ^ r) * 16 + c * 4;
            int sw1 = ((2 * ks + 1) ^ r) * 16 + c * 4;
            unsigned a[4] = {p[4 * ks], p[4 * ks + 1], p[4 * ks + 2], p[4 * ks + 3]};
#pragma unroll
            for (int dn = 0; dn < 16; dn++) {
                const char* pb = sv + (dn * 8 + r) * 128;
                unsigned bb[2];
                bb[0] = *(const unsigned*)(pb + sw0);
                bb[1] = *(const unsigned*)(pb + sw1);
                mma_f16(acc_o[dn], a, bb);
            }
        }
    }

    // ---- cross-slice reduction + normalize + write ----
    __syncthreads();
    float* red = (float*)(sm + FSM_K);   // 64KB, K stages retired

    if (wn == 1) {
        float* dst = red + wm * 2048;    // 16 rows x 128 floats
#pragma unroll
        for (int dn = 0; dn < 16; dn++) {
            *(float2*)(dst + r * 128 + dn * 8 + 2 * c)       = make_float2(acc_o[dn][0], acc_o[dn][1]);
            *(float2*)(dst + (r + 8) * 128 + dn * 8 + 2 * c) = make_float2(acc_o[dn][2], acc_o[dn][3]);
        }
    }
    l0 += __shfl_xor_sync(0xffffffffu, l0, 1);
    l0 += __shfl_xor_sync(0xffffffffu, l0, 2);
    l1 += __shfl_xor_sync(0xffffffffu, l1, 1);
    l1 += __shfl_xor_sync(0xffffffffu, l1, 2);
    if (c == 0) {
        lsum[wn * 128 + wm * 16 + r]     = l0;
        lsum[wn * 128 + wm * 16 + r + 8] = l1;
    }
    __syncthreads();

    if (wn == 0) {
        int row0 = wm * 16 + r;
        float inv0 = 1.f / (lsum[row0]     + lsum[128 + row0]);
        float inv1 = 1.f / (lsum[row0 + 8] + lsum[128 + row0 + 8]);
        const float* src = red + wm * 2048;
        __half* o0 = g_attn + (size_t)(bm * 128 + row0) * QS + h * 128;
        __half* o1 = g_attn + (size_t)(bm * 128 + row0 + 8) * QS + h * 128;
#pragma unroll
        for (int dn = 0; dn < 16; dn++) {
            int nc = dn * 8 + 2 * c;
            float2 s0 = *(const float2*)(src + r * 128 + nc);
            float2 s1 = *(const float2*)(src + (r + 8) * 128 + nc);
            __half2 h0 = __floats2half2_rn((acc_o[dn][0] + s0.x) * inv0,
                                           (acc_o[dn][1] + s0.y) * inv0);
            __half2 h1 = __floats2half2_rn((acc_o[dn][2] + s1.x) * inv1,
                                           (acc_o[dn][3] + s1.y) * inv1);
            *(__half2*)(o0 + nc) = h0;
            *(__half2*)(o1 + nc) = h1;
        }
    }
}

// ---------------- fp32 -> fp16 conversion ----------------
__global__ void h_conv(const float4* __restrict__ s, uint2* __restrict__ d, int n4) {
    int i = blockIdx.x * 256 + threadIdx.x;
    int stride = gridDim.x * 256;
    for (; i < n4; i += stride) {
        float4 v = s[i];
        __half2 lo = __floats2half2_rn(v.x, v.y);
        __half2 hi = __floats2half2_rn(v.z, v.w);
        uint2 o;
        o.x = *(unsigned*)&lo;
        o.y = *(unsigned*)&hi;
        d[i] = o;
    }
}

// ---------------- inv_freq ----------------
__global__ void init_invf() {
    int i = threadIdx.x;
    if (i < 64)
        g_invf[i] = (float)exp(-(double)i * (log(10000.0) / 64.0));
}

// ---------------- RMSNorm + RoPE + reorder (fp16 outputs; q pre-scaled) ----------------
__global__ __launch_bounds__(128) void norm_rope(
    const int* __restrict__ positions,
    const float* __restrict__ qw, const float* __restrict__ kw)
{
    int t = blockIdx.x, hh = blockIdx.y, d = threadIdx.x;

    if (hh >= 36) {
        int kvh = hh - 36;
        float v = g_qkv[(long long)t * QKVN + QS + KVS + kvh * HD + d];
        g_vt[((long long)kvh * HD + d) * TT + t] = __float2half_rn(v);
        return;
    }

    float x;
    if (hh < 32) x = g_qkv[(long long)t * QKVN + hh * HD + d];
    else         x = g_qkv[(long long)t * QKVN + QS + (hh - 32) * HD + d];

    __shared__ float red[4];
    __shared__ float ybuf[HD];
    float s = x * x;
#pragma unroll
    for (int o = 16; o; o >>= 1) s += __shfl_xor_sync(0xffffffffu, s, o);
    if ((d & 31) == 0) red[d >> 5] = s;
    __syncthreads();
    float tot = red[0] + red[1] + red[2] + red[3];

    const float* w = (hh < 32) ? qw : kw;
    float y = x * rsqrtf(tot * (1.0f / HD) + 1e-6f) * w[d];

    ybuf[d] = y;
    __syncthreads();

    int i = d & 63;
    float pos = (float)positions[t];
    float ang = pos * g_invf[i];
    float cs = cosf(ang), sn = sinf(ang);
    float out;
    if (d < 64) out = y * cs - ybuf[d + 64] * sn;
    else        out = y * cs + ybuf[d - 64] * sn;

    if (hh < 32) g_q[((long long)hh * TT + t) * HD + d] = __float2half_rn(out * ATT_SCALE);
    else         g_k[((long long)(hh - 32) * TT + t) * HD + d] = __float2half_rn(out);
}

// ---------------- launcher ----------------
extern "C" void kernel_launch(void* const* d_in, const int* in_sizes, int n_in,
                              void* d_out, int out_size)
{
    const int* positions = (const int*)d_in[0];   // int32 (JAX x64 disabled)
    const float* hidden = (const float*)d_in[1];
    const float* w_qkv  = (const float*)d_in[2];
    const float* w_o    = (const float*)d_in[3];
    const float* qw     = (const float*)d_in[4];
    const float* kw     = (const float*)d_in[5];
    float* out = (float*)d_out;

    float *p_qkv;
    __half *p_attn, *p_hidh, *p_wqkvh, *p_woh;
    cudaGetSymbolAddress((void**)&p_qkv,   g_qkv);
    cudaGetSymbolAddress((void**)&p_attn,  g_attn);
    cudaGetSymbolAddress((void**)&p_hidh,  g_hidh);
    cudaGetSymbolAddress((void**)&p_wqkvh, g_wqkvh);
    cudaGetSymbolAddress((void**)&p_woh,   g_woh);

    cudaFuncSetAttribute(gemm_h, cudaFuncAttributeMaxDynamicSharedMemorySize, SM_TOT);
    cudaFuncSetAttribute(flash_kernel, cudaFuncAttributeMaxDynamicSharedMemorySize, FSM_TOT);

    init_invf<<<1, 64>>>();

    // 0) fp16 conversions of external GEMM operands
    h_conv<<<1024, 256>>>((const float4*)hidden, (uint2*)p_hidh,  TT * HIDDEN / 4);
    h_conv<<<1024, 256>>>((const float4*)w_qkv,  (uint2*)p_wqkvh, QKVN * HIDDEN / 4);
    h_conv<<<1024, 256>>>((const float4*)w_o,    (uint2*)p_woh,   HIDDEN * QS / 4);

    // 1) QKV projection (fp32 out)
    gemm_h<<<dim3(QKVN / BN, TT / BM, 1), 256, SM_TOT>>>(
        p_hidh, p_wqkvh, p_qkv, HIDDEN, HIDDEN, HIDDEN, QKVN, 1.0f);

    // 2) RMSNorm + RoPE + reorder (fp16; q pre-scaled by d^-1/2)
    norm_rope<<<dim3(TT, 40), 128>>>(positions, qw, kw);

    // 3) fused flash attention -> g_attn (fp16)
    flash_kernel<<<512, 512, FSM_TOT>>>();

    // 4) output projection (fp32 out)
    gemm_h<<<dim3(HIDDEN / BN, TT / BM, 1), 256, SM_TOT>>>(
        p_attn, p_woh, out, QS, QS, QS, HIDDEN, 1.0f);
}

// round 8
// speedup vs baseline: 4.0582x; 1.0402x over previous
#include <cuda_runtime.h>
#include <cuda_fp16.h>
#include <math.h>
#include <float.h>
#include <stdint.h>

#define TT 2048
#define HIDDEN 2048
#define NH 32
#define NKV 4
#define HD 128
#define QS (NH*HD)        // 4096
#define KVS (NKV*HD)      // 512
#define QKVN (QS + 2*KVS) // 5120

// ---------------- scratch (static device globals; no allocs) ----------------
__device__ __half g_q   [(size_t)NH * TT * HD];   //  16 MB [h][t][d]  (pre-scaled by d^-1/2)
__device__ __half g_k   [(size_t)NKV * TT * HD];  //   2 MB [kv][t][d]
__device__ __half g_vt  [(size_t)NKV * HD * TT];  //   2 MB [kv][d][t]
__device__ __half g_attn[(size_t)TT * QS];        //  16 MB [t][h*128+d]
__device__ __half g_hidh [(size_t)TT * HIDDEN];   //   8 MB fp16(hidden)
__device__ __half g_wqkvh[(size_t)QKVN * HIDDEN]; //  20 MB fp16(w_qkv)
__device__ __half g_woh  [(size_t)HIDDEN * QS];   //  16 MB fp16(w_o)
__device__ float  g_invf[64];

#define ATT_SCALE 0.08838834764831845f
#define EXP_SHIFT 4.0f

// ---------------- helpers ----------------
__device__ __forceinline__ uint32_t smem_u32(const void* p) {
    uint32_t a;
    asm("{ .reg .u64 t; cvta.to.shared.u64 t, %1; cvt.u32.u64 %0, t; }" : "=r"(a) : "l"(p));
    return a;
}
__device__ __forceinline__ void cp16(uint32_t dst, const void* src) {
    asm volatile("cp.async.cg.shared.global [%0], [%1], 16;" :: "r"(dst), "l"(src));
}
__device__ __forceinline__ void mma_f16(float* d, const unsigned* a, const unsigned* b) {
    asm volatile(
        "mma.sync.aligned.m16n8k16.row.col.f32.f16.f16.f32 "
        "{%0,%1,%2,%3}, {%4,%5,%6,%7}, {%8,%9}, {%0,%1,%2,%3};\n"
        : "+f"(d[0]), "+f"(d[1]), "+f"(d[2]), "+f"(d[3])
        : "r"(a[0]), "r"(a[1]), "r"(a[2]), "r"(a[3]), "r"(b[0]), "r"(b[1]));
}
__device__ __forceinline__ void ldsm4(unsigned* r, uint32_t addr) {
    asm volatile("ldmatrix.sync.aligned.m8n8.x4.shared.b16 {%0,%1,%2,%3}, [%4];"
        : "=r"(r[0]), "=r"(r[1]), "=r"(r[2]), "=r"(r[3]) : "r"(addr));
}

// ================= dense fp16 TN GEMM (QKV fused-epilogue + O-proj) =================
#define STAGES 3
#define TILE_BYTES 16384
#define STAGE_BYTES 32768
#define SM_TOT (STAGES*STAGE_BYTES + 512)
#define BM 128
#define BN 128

// mode 0: plain fp32 C out
// mode 1: fused QKV epilogue: bn = head (0-31 q, 32-35 k, 36-39 v); RMSNorm+RoPE -> g_q/g_k,
//         transpose -> g_vt. C unused.
__global__ __launch_bounds__(256, 2) void gemm_h(
    const __half* __restrict__ A, const __half* __restrict__ B, float* __restrict__ C,
    int K, int lda, int ldb, int ldc, float scale,
    const int* __restrict__ positions, const float* __restrict__ qw,
    const float* __restrict__ kw, int mode)
{
    int bm = blockIdx.y, bn = blockIdx.x;

    extern __shared__ char smem[];
    uint32_t sbase = smem_u32(smem);

    int tid  = threadIdx.x;
    int warp = tid >> 5, lane = tid & 31;
    int wm = warp & 3, wn = warp >> 2;
    int r = lane >> 2, c = lane & 3;

    float acc[2][8][4];
#pragma unroll
    for (int i = 0; i < 2; i++)
#pragma unroll
        for (int j = 0; j < 8; j++)
#pragma unroll
            for (int k = 0; k < 4; k++) acc[i][j][k] = 0.f;

    int nkt = K >> 6;
    const __half* Ab = A + (long long)bm * BM * lda;
    const __half* Bb = B + (long long)bn * BN * ldb;

    int sm_ = tid >> 1;
    int scb = (tid & 1) * 4;
    long long arow = (long long)sm_ * lda;
    long long brow = (long long)sm_ * ldb;

#pragma unroll
    for (int p = 0; p < STAGES - 1; p++) {
        if (p < nkt) {
            int kb = p << 6;
            uint32_t aD = sbase + p * STAGE_BYTES + sm_ * 128;
            uint32_t bD = aD + TILE_BYTES;
            const __half* as = Ab + arow + kb + scb * 8;
            const __half* bs = Bb + brow + kb + scb * 8;
#pragma unroll
            for (int j = 0; j < 4; j++) {
                int sw = ((scb + j) ^ (sm_ & 7)) * 16;
                cp16(aD + sw, as + j * 8);
                cp16(bD + sw, bs + j * 8);
            }
        }
        asm volatile("cp.async.commit_group;" ::: "memory");
    }

    for (int kt = 0; kt < nkt; kt++) {
        asm volatile("cp.async.wait_group 1;" ::: "memory");
        __syncthreads();

        if (kt + STAGES - 1 < nkt) {
            int kn = kt + STAGES - 1;
            int kb = kn << 6;
            uint32_t aD = sbase + (kn % STAGES) * STAGE_BYTES + sm_ * 128;
            uint32_t bD = aD + TILE_BYTES;
            const __half* as = Ab + arow + kb + scb * 8;
            const __half* bs = Bb + brow + kb + scb * 8;
#pragma unroll
            for (int j = 0; j < 4; j++) {
                int sw = ((scb + j) ^ (sm_ & 7)) * 16;
                cp16(aD + sw, as + j * 8);
                cp16(bD + sw, bs + j * 8);
            }
        }
        asm volatile("cp.async.commit_group;" ::: "memory");

        const char* sa  = smem + (kt % STAGES) * STAGE_BYTES;
        const char* sbm = sa + TILE_BYTES;

#pragma unroll
        for (int ks = 0; ks < 4; ks++) {
            int sw0 = ((2 * ks)     ^ r) * 16 + c * 4;
            int sw1 = ((2 * ks + 1) ^ r) * 16 + c * 4;
            unsigned a[2][4];
#pragma unroll
            for (int mt = 0; mt < 2; mt++) {
                const char* pa = sa + (wm * 32 + mt * 16 + r) * 128;
                a[mt][0] = *(const unsigned*)(pa + sw0);
                a[mt][1] = *(const unsigned*)(pa + 8 * 128 + sw0);
                a[mt][2] = *(const unsigned*)(pa + sw1);
                a[mt][3] = *(const unsigned*)(pa + 8 * 128 + sw1);
            }
            unsigned b[8][2];
#pragma unroll
            for (int nt = 0; nt < 8; nt++) {
                const char* pb = sbm + (wn * 64 + nt * 8 + r) * 128;
                b[nt][0] = *(const unsigned*)(pb + sw0);
                b[nt][1] = *(const unsigned*)(pb + sw1);
            }
#pragma unroll
            for (int mt = 0; mt < 2; mt++)
#pragma unroll
                for (int nt = 0; nt < 8; nt++)
                    mma_f16(acc[mt][nt], a[mt], b[nt]);
        }
    }

    asm volatile("cp.async.wait_group 0;" ::: "memory");

    if (mode == 0) {
#pragma unroll
        for (int mt = 0; mt < 2; mt++) {
            int m0 = bm * BM + wm * 32 + mt * 16 + r;
#pragma unroll
            for (int nt = 0; nt < 8; nt++) {
                int n0 = bn * BN + wn * 64 + nt * 8 + 2 * c;
                *(float2*)(C + (long long)m0 * ldc + n0) =
                    make_float2(acc[mt][nt][0] * scale, acc[mt][nt][1] * scale);
                *(float2*)(C + (long long)(m0 + 8) * ldc + n0) =
                    make_float2(acc[mt][nt][2] * scale, acc[mt][nt][3] * scale);
            }
        }
        return;
    }

    // ---- fused QKV epilogue: acc -> smem buf (128 x 132 fp32), then norm/rope/transpose ----
    __syncthreads();
    float* buf = (float*)smem;
#pragma unroll
    for (int mt = 0; mt < 2; mt++) {
        int mrow = wm * 32 + mt * 16 + r;
#pragma unroll
        for (int nt = 0; nt < 8; nt++) {
            int nc = wn * 64 + nt * 8 + 2 * c;
            *(float2*)(buf + mrow * 132 + nc)       = make_float2(acc[mt][nt][0], acc[mt][nt][1]);
            *(float2*)(buf + (mrow + 8) * 132 + nc) = make_float2(acc[mt][nt][2], acc[mt][nt][3]);
        }
    }
    __syncthreads();

    int h = bn;
    if (h < 36) {
        int row = tid >> 1, half = tid & 1;
        int t = bm * 128 + row;
        const float* own = buf + row * 132 + half * 64;
        const float* par = buf + row * 132 + (half ^ 1) * 64;

        float ss = 0.f;
#pragma unroll
        for (int i = 0; i < 16; i++) {
            float4 v = *(const float4*)(own + i * 4);
            ss += v.x * v.x + v.y * v.y + v.z * v.z + v.w * v.w;
        }
        ss += __shfl_xor_sync(0xffffffffu, ss, 1);
        float rinv = rsqrtf(ss * (1.f / 128.f) + 1e-6f);

        const float* w_ = (h < 32) ? qw : kw;
        float pos = (float)positions[t];
        float osc = (h < 32) ? ATT_SCALE : 1.f;
        float sgn = half ? 1.f : -1.f;
        __half* outp;
        if (h < 32) outp = g_q + ((size_t)h * TT + t) * HD + half * 64;
        else        outp = g_k + ((size_t)(h - 32) * TT + t) * HD + half * 64;

#pragma unroll 8
        for (int i = 0; i < 64; i += 2) {
            float cs0 = 0.f, sn0 = 0.f, cs1 = 0.f, sn1 = 0.f;
            if (!(lane & 1)) {
                float a0 = pos * g_invf[i], a1 = pos * g_invf[i + 1];
                cs0 = cosf(a0); sn0 = sinf(a0);
                cs1 = cosf(a1); sn1 = sinf(a1);
            }
            cs0 = __shfl_sync(0xffffffffu, cs0, lane & ~1);
            sn0 = __shfl_sync(0xffffffffu, sn0, lane & ~1);
            cs1 = __shfl_sync(0xffffffffu, cs1, lane & ~1);
            sn1 = __shfl_sync(0xffffffffu, sn1, lane & ~1);
            float y0 = own[i]     * rinv * w_[half * 64 + i];
            float y1 = own[i + 1] * rinv * w_[half * 64 + i + 1];
            float z0 = par[i]     * rinv * w_[(half ^ 1) * 64 + i];
            float z1 = par[i + 1] * rinv * w_[(half ^ 1) * 64 + i + 1];
            float o0 = (y0 * cs0 + sgn * z0 * sn0) * osc;
            float o1 = (y1 * cs1 + sgn * z1 * sn1) * osc;
            *(__half2*)(outp + i) = __floats2half2_rn(o0, o1);
        }
    } else {
        int d = tid >> 1, thalf = tid & 1;
        int kvh = h - 36;
        __half* vp = g_vt + ((size_t)kvh * HD + d) * TT + (size_t)bm * 128 + thalf * 64;
#pragma unroll 8
        for (int j2 = 0; j2 < 64; j2 += 2) {
            float v0 = buf[(thalf * 64 + j2) * 132 + d];
            float v1 = buf[(thalf * 64 + j2 + 1) * 132 + d];
            *(__half2*)(vp + j2) = __floats2half2_rn(v0, v1);
        }
    }
}

// ================= fused flash attention (ldmatrix fragment loads) =================
#define FSM_Q 0
#define FSM_K 32768
#define FSM_V (32768 + 65536)
#define FSM_L (FSM_V + 65536)
#define FSM_TOT (FSM_L + 1024 + 128)

__device__ __forceinline__ void flash_load_tile128(
    uint32_t sdst, const __half* src, int ld, int tid)
{
#pragma unroll
    for (int i = 0; i < 4; i++) {
        int li = tid + 512 * i;
        int row = li >> 4, cc = li & 15;
        uint32_t dst = sdst + (cc >> 3) * 16384 + row * 128 + (((cc & 7) ^ (row & 7)) * 16);
        cp16(dst, src + (long long)row * ld + cc * 8);
    }
}

__global__ __launch_bounds__(512, 1) void flash_kernel()
{
    int b = blockIdx.x;
    int bm = 15 - (b >> 5);     // heavy blocks first
    int h  = b & 31;
    int kvh = h >> 3;

    extern __shared__ char sm[];
    uint32_t sbase = smem_u32(sm);
    float* lsum = (float*)(sm + FSM_L);

    int tid = threadIdx.x;
    int w = tid >> 5, lane = tid & 31;
    int wm = w & 7, wn = w >> 3;
    int r = lane >> 2, c = lane & 3;

    // ldmatrix lane geometry
    int am  = wm * 16 + ((lane >> 3) & 1) * 8 + (lane & 7);   // A tile row
    int am7 = am & 7;
    int ahi = lane >> 4;                                       // A chunk hi-bit
    uint32_t aoff = (uint32_t)am * 128u;
    int bro = ((lane >> 4) << 3) + (lane & 7);                 // B row offset in 16-row pair
    int bcb = (lane >> 3) & 1;                                 // B chunk bit
    int bb7 = bro & 7;

    const __half* qsrc = g_q + ((size_t)h * TT + (size_t)bm * 128) * HD;
    const __half* ksrc = g_k + (size_t)kvh * TT * HD;
    const __half* vsrc = g_vt + (size_t)kvh * HD * TT;

    flash_load_tile128(sbase + FSM_Q, qsrc, HD, tid);
    flash_load_tile128(sbase + FSM_K, ksrc, HD, tid);
#pragma unroll
    for (int i = 0; i < 4; i++) {
        int li = tid + 512 * i;
        int row = li >> 4, cc = li & 15;
        uint32_t dst = sbase + FSM_V + (cc >> 3) * 16384 + row * 128 + (((cc & 7) ^ (row & 7)) * 16);
        cp16(dst, vsrc + (size_t)row * TT + cc * 8);
    }
    asm volatile("cp.async.commit_group;" ::: "memory");

    float acc_o[16][4];
#pragma unroll
    for (int i = 0; i < 16; i++)
#pragma unroll
        for (int k = 0; k < 4; k++) acc_o[i][k] = 0.f;
    float l0 = 0.f, l1 = 0.f;

    int mrow0 = wm * 16 + r;

    for (int j = 0; j <= bm; j++) {
        int st = j & 1;
        asm volatile("cp.async.wait_group 0;" ::: "memory");
        __syncthreads();

        if (j < bm) {
            int jn = j + 1;
            flash_load_tile128(sbase + FSM_K + (st ^ 1) * 32768,
                               ksrc + (size_t)jn * 128 * HD, HD, tid);
#pragma unroll
            for (int i = 0; i < 4; i++) {
                int li = tid + 512 * i;
                int row = li >> 4, cc = li & 15;
                uint32_t dst = sbase + FSM_V + (st ^ 1) * 32768 + (cc >> 3) * 16384
                             + row * 128 + (((cc & 7) ^ (row & 7)) * 16);
                cp16(dst, vsrc + (size_t)row * TT + jn * 128 + cc * 8);
            }
        }
        asm volatile("cp.async.commit_group;" ::: "memory");

        // ---- S = Q @ K^T ----
        float acc_s[8][4];
#pragma unroll
        for (int i = 0; i < 8; i++)
#pragma unroll
            for (int k = 0; k < 4; k++) acc_s[i][k] = 0.f;

        uint32_t squ = sbase + FSM_Q;
        uint32_t sku = sbase + FSM_K + st * 32768;
#pragma unroll
        for (int kt = 0; kt < 2; kt++) {
#pragma unroll
            for (int ks = 0; ks < 4; ks++) {
                unsigned a[4];
                ldsm4(a, squ + kt * 16384 + aoff + ((unsigned)((2 * ks + ahi) ^ am7) << 4));
#pragma unroll
                for (int ntp = 0; ntp < 4; ntp++) {
                    unsigned bb[4];
                    ldsm4(bb, sku + kt * 16384 + (unsigned)(wn * 64 + ntp * 16 + bro) * 128
                              + ((unsigned)((2 * ks + bcb) ^ bb7) << 4));
                    mma_f16(acc_s[2 * ntp],     a, bb);
                    mma_f16(acc_s[2 * ntp + 1], a, bb + 2);
                }
            }
        }

        // ---- exp + causal mask + pack + rowsums ----
        unsigned p[16];
        bool diag = (j == bm);
#pragma unroll
        for (int nt = 0; nt < 8; nt++) {
            int n0 = wn * 64 + nt * 8 + 2 * c;
            float v0 = __expf(acc_s[nt][0] - EXP_SHIFT);
            float v1 = __expf(acc_s[nt][1] - EXP_SHIFT);
            float v2 = __expf(acc_s[nt][2] - EXP_SHIFT);
            float v3 = __expf(acc_s[nt][3] - EXP_SHIFT);
            if (diag) {
                if (n0     > mrow0)     v0 = 0.f;
                if (n0 + 1 > mrow0)     v1 = 0.f;
                if (n0     > mrow0 + 8) v2 = 0.f;
                if (n0 + 1 > mrow0 + 8) v3 = 0.f;
            }
            l0 += v0 + v1;
            l1 += v2 + v3;
            __half2 h01 = __floats2half2_rn(v0, v1);
            __half2 h23 = __floats2half2_rn(v2, v3);
            p[2 * nt]     = *(unsigned*)&h01;
            p[2 * nt + 1] = *(unsigned*)&h23;
        }

        // ---- O += P @ V ----
        uint32_t svu = sbase + FSM_V + st * 32768 + wn * 16384;
#pragma unroll
        for (int ks = 0; ks < 4; ks++) {
            unsigned a[4] = {p[4 * ks], p[4 * ks + 1], p[4 * ks + 2], p[4 * ks + 3]};
#pragma unroll
            for (int dnp = 0; dnp < 8; dnp++) {
                unsigned bb[4];
                ldsm4(bb, svu + (unsigned)(dnp * 16 + bro) * 128
                          + ((unsigned)((2 * ks + bcb) ^ bb7) << 4));
                mma_f16(acc_o[2 * dnp],     a, bb);
                mma_f16(acc_o[2 * dnp + 1], a, bb + 2);
            }
        }
    }

    // ---- cross-slice reduction + normalize + write ----
    __syncthreads();
    float* red = (float*)(sm + FSM_K);

    if (wn == 1) {
        float* dst = red + wm * 2048;
#pragma unroll
        for (int dn = 0; dn < 16; dn++) {
            *(float2*)(dst + r * 128 + dn * 8 + 2 * c)       = make_float2(acc_o[dn][0], acc_o[dn][1]);
            *(float2*)(dst + (r + 8) * 128 + dn * 8 + 2 * c) = make_float2(acc_o[dn][2], acc_o[dn][3]);
        }
    }
    l0 += __shfl_xor_sync(0xffffffffu, l0, 1);
    l0 += __shfl_xor_sync(0xffffffffu, l0, 2);
    l1 += __shfl_xor_sync(0xffffffffu, l1, 1);
    l1 += __shfl_xor_sync(0xffffffffu, l1, 2);
    if (c == 0) {
        lsum[wn * 128 + wm * 16 + r]     = l0;
        lsum[wn * 128 + wm * 16 + r + 8] = l1;
    }
    __syncthreads();

    if (wn == 0) {
        int row0 = wm * 16 + r;
        float inv0 = 1.f / (lsum[row0]     + lsum[128 + row0]);
        float inv1 = 1.f / (lsum[row0 + 8] + lsum[128 + row0 + 8]);
        const float* src = red + wm * 2048;
        __half* o0 = g_attn + (size_t)(bm * 128 + row0) * QS + h * 128;
        __half* o1 = g_attn + (size_t)(bm * 128 + row0 + 8) * QS + h * 128;
#pragma unroll
        for (int dn = 0; dn < 16; dn++) {
            int nc = dn * 8 + 2 * c;
            float2 s0 = *(const float2*)(src + r * 128 + nc);
            float2 s1 = *(const float2*)(src + (r + 8) * 128 + nc);
            *(__half2*)(o0 + nc) = __floats2half2_rn((acc_o[dn][0] + s0.x) * inv0,
                                                     (acc_o[dn][1] + s0.y) * inv0);
            *(__half2*)(o1 + nc) = __floats2half2_rn((acc_o[dn][2] + s1.x) * inv1,
                                                     (acc_o[dn][3] + s1.y) * inv1);
        }
    }
}

// ---------------- fp32 -> fp16 conversion ----------------
__global__ void h_conv(const float4* __restrict__ s, uint2* __restrict__ d, int n4) {
    int i = blockIdx.x * 256 + threadIdx.x;
    int stride = gridDim.x * 256;
    for (; i < n4; i += stride) {
        float4 v = s[i];
        __half2 lo = __floats2half2_rn(v.x, v.y);
        __half2 hi = __floats2half2_rn(v.z, v.w);
        uint2 o;
        o.x = *(unsigned*)&lo;
        o.y = *(unsigned*)&hi;
        d[i] = o;
    }
}

// ---------------- inv_freq ----------------
__global__ void init_invf() {
    int i = threadIdx.x;
    if (i < 64)
        g_invf[i] = (float)exp(-(double)i * (log(10000.0) / 64.0));
}

// ---------------- launcher ----------------
extern "C" void kernel_launch(void* const* d_in, const int* in_sizes, int n_in,
                              void* d_out, int out_size)
{
    const int* positions = (const int*)d_in[0];   // int32 (JAX x64 disabled)
    const float* hidden = (const float*)d_in[1];
    const float* w_qkv  = (const float*)d_in[2];
    const float* w_o    = (const float*)d_in[3];
    const float* qw     = (const float*)d_in[4];
    const float* kw     = (const float*)d_in[5];
    float* out = (float*)d_out;

    __half *p_attn, *p_hidh, *p_wqkvh, *p_woh;
    cudaGetSymbolAddress((void**)&p_attn,  g_attn);
    cudaGetSymbolAddress((void**)&p_hidh,  g_hidh);
    cudaGetSymbolAddress((void**)&p_wqkvh, g_wqkvh);
    cudaGetSymbolAddress((void**)&p_woh,   g_woh);

    cudaFuncSetAttribute(gemm_h, cudaFuncAttributeMaxDynamicSharedMemorySize, SM_TOT);
    cudaFuncSetAttribute(flash_kernel, cudaFuncAttributeMaxDynamicSharedMemorySize, FSM_TOT);

    init_invf<<<1, 64>>>();

    // 0) fp16 conversions
    h_conv<<<1024, 256>>>((const float4*)hidden, (uint2*)p_hidh,  TT * HIDDEN / 4);
    h_conv<<<1024, 256>>>((const float4*)w_qkv,  (uint2*)p_wqkvh, QKVN * HIDDEN / 4);
    h_conv<<<1024, 256>>>((const float4*)w_o,    (uint2*)p_woh,   HIDDEN * QS / 4);

    // 1) QKV projection with fused RMSNorm+RoPE+reorder epilogue
    gemm_h<<<dim3(QKVN / BN, TT / BM, 1), 256, SM_TOT>>>(
        p_hidh, p_wqkvh, nullptr, HIDDEN, HIDDEN, HIDDEN, 0, 1.0f,
        positions, qw, kw, 1);

    // 2) fused flash attention -> g_attn (fp16)
    flash_kernel<<<512, 512, FSM_TOT>>>();

    // 3) output projection (fp32 out)
    gemm_h<<<dim3(HIDDEN / BN, TT / BM, 1), 256, SM_TOT>>>(
        p_attn, p_woh, out, QS, QS, QS, HIDDEN, 1.0f,
        nullptr, nullptr, nullptr, 0);
}

// round 9
// speedup vs baseline: 4.4096x; 1.0866x over previous
#include <cuda_runtime.h>
#include <cuda_fp16.h>
#include <math.h>
#include <float.h>
#include <stdint.h>

#define TT 2048
#define HIDDEN 2048
#define NH 32
#define NKV 4
#define HD 128
#define QS (NH*HD)        // 4096
#define KVS (NKV*HD)      // 512
#define QKVN (QS + 2*KVS) // 5120

// ---------------- scratch (static device globals; no allocs) ----------------
__device__ __half g_q   [(size_t)NH * TT * HD];   //  16 MB [h][t][d]  (pre-scaled by d^-1/2)
__device__ __half g_k   [(size_t)NKV * TT * HD];  //   2 MB [kv][t][d]
__device__ __half g_vt  [(size_t)NKV * HD * TT];  //   2 MB [kv][d][t]
__device__ __half g_attn[(size_t)TT * QS];        //  16 MB [t][h*128+d]
__device__ __half g_hidh [(size_t)TT * HIDDEN];   //   8 MB fp16(hidden)
__device__ __half g_wqkvh[(size_t)QKVN * HIDDEN]; //  20 MB fp16(w_qkv)
__device__ __half g_woh  [(size_t)HIDDEN * QS];   //  16 MB fp16(w_o)
__device__ float  g_invf[64];

#define ATT_SCALE 0.08838834764831845f
#define EXP_SHIFT 4.0f

// ---------------- helpers ----------------
__device__ __forceinline__ uint32_t smem_u32(const void* p) {
    uint32_t a;
    asm("{ .reg .u64 t; cvta.to.shared.u64 t, %1; cvt.u32.u64 %0, t; }" : "=r"(a) : "l"(p));
    return a;
}
__device__ __forceinline__ void cp16(uint32_t dst, const void* src) {
    asm volatile("cp.async.cg.shared.global [%0], [%1], 16;" :: "r"(dst), "l"(src));
}
__device__ __forceinline__ void mma_f16(float* d, const unsigned* a, const unsigned* b) {
    asm volatile(
        "mma.sync.aligned.m16n8k16.row.col.f32.f16.f16.f32 "
        "{%0,%1,%2,%3}, {%4,%5,%6,%7}, {%8,%9}, {%0,%1,%2,%3};\n"
        : "+f"(d[0]), "+f"(d[1]), "+f"(d[2]), "+f"(d[3])
        : "r"(a[0]), "r"(a[1]), "r"(a[2]), "r"(a[3]), "r"(b[0]), "r"(b[1]));
}
__device__ __forceinline__ void ldsm4(unsigned* r, uint32_t addr) {
    asm volatile("ldmatrix.sync.aligned.m8n8.x4.shared.b16 {%0,%1,%2,%3}, [%4];"
        : "=r"(r[0]), "=r"(r[1]), "=r"(r[2]), "=r"(r[3]) : "r"(addr));
}

// ================= dense fp16 TN GEMM (QKV fused-epilogue + O-proj) =================
#define STAGES 3
#define TILE_BYTES 16384
#define STAGE_BYTES 32768
#define SM_TOT (STAGES*STAGE_BYTES + 512)
#define BM 128
#define BN 128

// mode 0: plain fp32 C out
// mode 1: fused QKV epilogue: bn = head (0-31 q, 32-35 k, 36-39 v); RMSNorm+RoPE -> g_q/g_k,
//         transpose -> g_vt. C unused.
__global__ __launch_bounds__(256, 2) void gemm_h(
    const __half* __restrict__ A, const __half* __restrict__ B, float* __restrict__ C,
    int K, int lda, int ldb, int ldc, float scale,
    const int* __restrict__ positions, const float* __restrict__ qw,
    const float* __restrict__ kw, int mode)
{
    int bm = blockIdx.y, bn = blockIdx.x;

    extern __shared__ char smem[];
    uint32_t sbase = smem_u32(smem);

    int tid  = threadIdx.x;
    int warp = tid >> 5, lane = tid & 31;
    int wm = warp & 3, wn = warp >> 2;
    int r = lane >> 2, c = lane & 3;

    // ldmatrix lane geometry (same as flash kernel)
    int arow_in = ((lane >> 3) & 1) * 8 + (lane & 7);   // row within 16-row tile
    int ahi = lane >> 4;                                 // chunk hi-bit
    int am7 = lane & 7;
    int bro = ((lane >> 4) << 3) + (lane & 7);           // B row within 16-row pair
    int bcb = (lane >> 3) & 1;
    int bb7 = lane & 7;

    float acc[2][8][4];
#pragma unroll
    for (int i = 0; i < 2; i++)
#pragma unroll
        for (int j = 0; j < 8; j++)
#pragma unroll
            for (int k = 0; k < 4; k++) acc[i][j][k] = 0.f;

    int nkt = K >> 6;
    const __half* Ab = A + (long long)bm * BM * lda;
    const __half* Bb = B + (long long)bn * BN * ldb;

    int sm_ = tid >> 1;
    int scb = (tid & 1) * 4;
    long long arow = (long long)sm_ * lda;
    long long brow = (long long)sm_ * ldb;

#pragma unroll
    for (int p = 0; p < STAGES - 1; p++) {
        if (p < nkt) {
            int kb = p << 6;
            uint32_t aD = sbase + p * STAGE_BYTES + sm_ * 128;
            uint32_t bD = aD + TILE_BYTES;
            const __half* as = Ab + arow + kb + scb * 8;
            const __half* bs = Bb + brow + kb + scb * 8;
#pragma unroll
            for (int j = 0; j < 4; j++) {
                int sw = ((scb + j) ^ (sm_ & 7)) * 16;
                cp16(aD + sw, as + j * 8);
                cp16(bD + sw, bs + j * 8);
            }
        }
        asm volatile("cp.async.commit_group;" ::: "memory");
    }

    for (int kt = 0; kt < nkt; kt++) {
        asm volatile("cp.async.wait_group 1;" ::: "memory");
        __syncthreads();

        if (kt + STAGES - 1 < nkt) {
            int kn = kt + STAGES - 1;
            int kb = kn << 6;
            uint32_t aD = sbase + (kn % STAGES) * STAGE_BYTES + sm_ * 128;
            uint32_t bD = aD + TILE_BYTES;
            const __half* as = Ab + arow + kb + scb * 8;
            const __half* bs = Bb + brow + kb + scb * 8;
#pragma unroll
            for (int j = 0; j < 4; j++) {
                int sw = ((scb + j) ^ (sm_ & 7)) * 16;
                cp16(aD + sw, as + j * 8);
                cp16(bD + sw, bs + j * 8);
            }
        }
        asm volatile("cp.async.commit_group;" ::: "memory");

        uint32_t sa  = sbase + (kt % STAGES) * STAGE_BYTES;
        uint32_t sbm = sa + TILE_BYTES;

#pragma unroll
        for (int ks = 0; ks < 4; ks++) {
            unsigned a[2][4];
#pragma unroll
            for (int mt = 0; mt < 2; mt++) {
                uint32_t row = (uint32_t)(wm * 32 + mt * 16 + arow_in);
                ldsm4(a[mt], sa + row * 128u + ((unsigned)((2 * ks + ahi) ^ am7) << 4));
            }
#pragma unroll
            for (int ntp = 0; ntp < 4; ntp++) {
                unsigned bb[4];
                uint32_t row = (uint32_t)(wn * 64 + ntp * 16 + bro);
                ldsm4(bb, sbm + row * 128u + ((unsigned)((2 * ks + bcb) ^ bb7) << 4));
#pragma unroll
                for (int mt = 0; mt < 2; mt++) {
                    mma_f16(acc[mt][2 * ntp],     a[mt], bb);
                    mma_f16(acc[mt][2 * ntp + 1], a[mt], bb + 2);
                }
            }
        }
    }

    asm volatile("cp.async.wait_group 0;" ::: "memory");

    if (mode == 0) {
#pragma unroll
        for (int mt = 0; mt < 2; mt++) {
            int m0 = bm * BM + wm * 32 + mt * 16 + r;
#pragma unroll
            for (int nt = 0; nt < 8; nt++) {
                int n0 = bn * BN + wn * 64 + nt * 8 + 2 * c;
                *(float2*)(C + (long long)m0 * ldc + n0) =
                    make_float2(acc[mt][nt][0] * scale, acc[mt][nt][1] * scale);
                *(float2*)(C + (long long)(m0 + 8) * ldc + n0) =
                    make_float2(acc[mt][nt][2] * scale, acc[mt][nt][3] * scale);
            }
        }
        return;
    }

    // ---- fused QKV epilogue: acc -> smem buf (128 x 132 fp32), then norm/rope/transpose ----
    __syncthreads();
    float* buf = (float*)smem;
#pragma unroll
    for (int mt = 0; mt < 2; mt++) {
        int mrow = wm * 32 + mt * 16 + r;
#pragma unroll
        for (int nt = 0; nt < 8; nt++) {
            int nc = wn * 64 + nt * 8 + 2 * c;
            *(float2*)(buf + mrow * 132 + nc)       = make_float2(acc[mt][nt][0], acc[mt][nt][1]);
            *(float2*)(buf + (mrow + 8) * 132 + nc) = make_float2(acc[mt][nt][2], acc[mt][nt][3]);
        }
    }
    __syncthreads();

    int h = bn;
    if (h < 36) {
        int row = tid >> 1, half = tid & 1;
        int t = bm * 128 + row;
        const float* own = buf + row * 132 + half * 64;
        const float* par = buf + row * 132 + (half ^ 1) * 64;

        float ss = 0.f;
#pragma unroll
        for (int i = 0; i < 16; i++) {
            float4 v = *(const float4*)(own + i * 4);
            ss += v.x * v.x + v.y * v.y + v.z * v.z + v.w * v.w;
        }
        ss += __shfl_xor_sync(0xffffffffu, ss, 1);
        float rinv = rsqrtf(ss * (1.f / 128.f) + 1e-6f);

        const float* w_ = (h < 32) ? qw : kw;
        float pos = (float)positions[t];
        float osc = (h < 32) ? ATT_SCALE : 1.f;
        float sgn = half ? 1.f : -1.f;
        __half* outp;
        if (h < 32) outp = g_q + ((size_t)h * TT + t) * HD + half * 64;
        else        outp = g_k + ((size_t)(h - 32) * TT + t) * HD + half * 64;

#pragma unroll 8
        for (int i = 0; i < 64; i += 2) {
            float cs0 = 0.f, sn0 = 0.f, cs1 = 0.f, sn1 = 0.f;
            if (!(lane & 1)) {
                float a0 = pos * g_invf[i], a1 = pos * g_invf[i + 1];
                cs0 = cosf(a0); sn0 = sinf(a0);
                cs1 = cosf(a1); sn1 = sinf(a1);
            }
            cs0 = __shfl_sync(0xffffffffu, cs0, lane & ~1);
            sn0 = __shfl_sync(0xffffffffu, sn0, lane & ~1);
            cs1 = __shfl_sync(0xffffffffu, cs1, lane & ~1);
            sn1 = __shfl_sync(0xffffffffu, sn1, lane & ~1);
            float y0 = own[i]     * rinv * w_[half * 64 + i];
            float y1 = own[i + 1] * rinv * w_[half * 64 + i + 1];
            float z0 = par[i]     * rinv * w_[(half ^ 1) * 64 + i];
            float z1 = par[i + 1] * rinv * w_[(half ^ 1) * 64 + i + 1];
            float o0 = (y0 * cs0 + sgn * z0 * sn0) * osc;
            float o1 = (y1 * cs1 + sgn * z1 * sn1) * osc;
            *(__half2*)(outp + i) = __floats2half2_rn(o0, o1);
        }
    } else {
        int d = tid >> 1, thalf = tid & 1;
        int kvh = h - 36;
        __half* vp = g_vt + ((size_t)kvh * HD + d) * TT + (size_t)bm * 128 + thalf * 64;
#pragma unroll 8
        for (int j2 = 0; j2 < 64; j2 += 2) {
            float v0 = buf[(thalf * 64 + j2) * 132 + d];
            float v1 = buf[(thalf * 64 + j2 + 1) * 132 + d];
            *(__half2*)(vp + j2) = __floats2half2_rn(v0, v1);
        }
    }
}

// ================= fused flash attention (ldmatrix fragment loads) =================
#define FSM_Q 0
#define FSM_K 32768
#define FSM_V (32768 + 65536)
#define FSM_L (FSM_V + 65536)
#define FSM_TOT (FSM_L + 1024 + 128)

__device__ __forceinline__ void flash_load_tile128(
    uint32_t sdst, const __half* src, int ld, int tid)
{
#pragma unroll
    for (int i = 0; i < 4; i++) {
        int li = tid + 512 * i;
        int row = li >> 4, cc = li & 15;
        uint32_t dst = sdst + (cc >> 3) * 16384 + row * 128 + (((cc & 7) ^ (row & 7)) * 16);
        cp16(dst, src + (long long)row * ld + cc * 8);
    }
}

__global__ __launch_bounds__(512, 1) void flash_kernel()
{
    int b = blockIdx.x;
    int bm = 15 - (b >> 5);     // heavy blocks first
    int h  = b & 31;
    int kvh = h >> 3;

    extern __shared__ char sm[];
    uint32_t sbase = smem_u32(sm);
    float* lsum = (float*)(sm + FSM_L);

    int tid = threadIdx.x;
    int w = tid >> 5, lane = tid & 31;
    int wm = w & 7, wn = w >> 3;
    int r = lane >> 2, c = lane & 3;

    int am  = wm * 16 + ((lane >> 3) & 1) * 8 + (lane & 7);
    int am7 = am & 7;
    int ahi = lane >> 4;
    uint32_t aoff = (uint32_t)am * 128u;
    int bro = ((lane >> 4) << 3) + (lane & 7);
    int bcb = (lane >> 3) & 1;
    int bb7 = bro & 7;

    const __half* qsrc = g_q + ((size_t)h * TT + (size_t)bm * 128) * HD;
    const __half* ksrc = g_k + (size_t)kvh * TT * HD;
    const __half* vsrc = g_vt + (size_t)kvh * HD * TT;

    flash_load_tile128(sbase + FSM_Q, qsrc, HD, tid);
    flash_load_tile128(sbase + FSM_K, ksrc, HD, tid);
#pragma unroll
    for (int i = 0; i < 4; i++) {
        int li = tid + 512 * i;
        int row = li >> 4, cc = li & 15;
        uint32_t dst = sbase + FSM_V + (cc >> 3) * 16384 + row * 128 + (((cc & 7) ^ (row & 7)) * 16);
        cp16(dst, vsrc + (size_t)row * TT + cc * 8);
    }
    asm volatile("cp.async.commit_group;" ::: "memory");

    float acc_o[16][4];
#pragma unroll
    for (int i = 0; i < 16; i++)
#pragma unroll
        for (int k = 0; k < 4; k++) acc_o[i][k] = 0.f;
    float l0 = 0.f, l1 = 0.f;

    int mrow0 = wm * 16 + r;

    for (int j = 0; j <= bm; j++) {
        int st = j & 1;
        asm volatile("cp.async.wait_group 0;" ::: "memory");
        __syncthreads();

        if (j < bm) {
            int jn = j + 1;
            flash_load_tile128(sbase + FSM_K + (st ^ 1) * 32768,
                               ksrc + (size_t)jn * 128 * HD, HD, tid);
#pragma unroll
            for (int i = 0; i < 4; i++) {
                int li = tid + 512 * i;
                int row = li >> 4, cc = li & 15;
                uint32_t dst = sbase + FSM_V + (st ^ 1) * 32768 + (cc >> 3) * 16384
                             + row * 128 + (((cc & 7) ^ (row & 7)) * 16);
                cp16(dst, vsrc + (size_t)row * TT + jn * 128 + cc * 8);
            }
        }
        asm volatile("cp.async.commit_group;" ::: "memory");

        // ---- S = Q @ K^T ----
        float acc_s[8][4];
#pragma unroll
        for (int i = 0; i < 8; i++)
#pragma unroll
            for (int k = 0; k < 4; k++) acc_s[i][k] = 0.f;

        uint32_t squ = sbase + FSM_Q;
        uint32_t sku = sbase + FSM_K + st * 32768;
#pragma unroll
        for (int kt = 0; kt < 2; kt++) {
#pragma unroll
            for (int ks = 0; ks < 4; ks++) {
                unsigned a[4];
                ldsm4(a, squ + kt * 16384 + aoff + ((unsigned)((2 * ks + ahi) ^ am7) << 4));
#pragma unroll
                for (int ntp = 0; ntp < 4; ntp++) {
                    unsigned bb[4];
                    ldsm4(bb, sku + kt * 16384 + (unsigned)(wn * 64 + ntp * 16 + bro) * 128
                              + ((unsigned)((2 * ks + bcb) ^ bb7) << 4));
                    mma_f16(acc_s[2 * ntp],     a, bb);
                    mma_f16(acc_s[2 * ntp + 1], a, bb + 2);
                }
            }
        }

        // ---- exp + causal mask + pack + rowsums ----
        unsigned p[16];
        bool diag = (j == bm);
#pragma unroll
        for (int nt = 0; nt < 8; nt++) {
            int n0 = wn * 64 + nt * 8 + 2 * c;
            float v0 = __expf(acc_s[nt][0] - EXP_SHIFT);
            float v1 = __expf(acc_s[nt][1] - EXP_SHIFT);
            float v2 = __expf(acc_s[nt][2] - EXP_SHIFT);
            float v3 = __expf(acc_s[nt][3] - EXP_SHIFT);
            if (diag) {
                if (n0     > mrow0)     v0 = 0.f;
                if (n0 + 1 > mrow0)     v1 = 0.f;
                if (n0     > mrow0 + 8) v2 = 0.f;
                if (n0 + 1 > mrow0 + 8) v3 = 0.f;
            }
            l0 += v0 + v1;
            l1 += v2 + v3;
            __half2 h01 = __floats2half2_rn(v0, v1);
            __half2 h23 = __floats2half2_rn(v2, v3);
            p[2 * nt]     = *(unsigned*)&h01;
            p[2 * nt + 1] = *(unsigned*)&h23;
        }

        // ---- O += P @ V ----
        uint32_t svu = sbase + FSM_V + st * 32768 + wn * 16384;
#pragma unroll
        for (int ks = 0; ks < 4; ks++) {
            unsigned a[4] = {p[4 * ks], p[4 * ks + 1], p[4 * ks + 2], p[4 * ks + 3]};
#pragma unroll
            for (int dnp = 0; dnp < 8; dnp++) {
                unsigned bb[4];
                ldsm4(bb, svu + (unsigned)(dnp * 16 + bro) * 128
                          + ((unsigned)((2 * ks + bcb) ^ bb7) << 4));
                mma_f16(acc_o[2 * dnp],     a, bb);
                mma_f16(acc_o[2 * dnp + 1], a, bb + 2);
            }
        }
    }

    // ---- cross-slice reduction + normalize + write ----
    __syncthreads();
    float* red = (float*)(sm + FSM_K);

    if (wn == 1) {
        float* dst = red + wm * 2048;
#pragma unroll
        for (int dn = 0; dn < 16; dn++) {
            *(float2*)(dst + r * 128 + dn * 8 + 2 * c)       = make_float2(acc_o[dn][0], acc_o[dn][1]);
            *(float2*)(dst + (r + 8) * 128 + dn * 8 + 2 * c) = make_float2(acc_o[dn][2], acc_o[dn][3]);
        }
    }
    l0 += __shfl_xor_sync(0xffffffffu, l0, 1);
    l0 += __shfl_xor_sync(0xffffffffu, l0, 2);
    l1 += __shfl_xor_sync(0xffffffffu, l1, 1);
    l1 += __shfl_xor_sync(0xffffffffu, l1, 2);
    if (c == 0) {
        lsum[wn * 128 + wm * 16 + r]     = l0;
        lsum[wn * 128 + wm * 16 + r + 8] = l1;
    }
    __syncthreads();

    if (wn == 0) {
        int row0 = wm * 16 + r;
        float inv0 = 1.f / (lsum[row0]     + lsum[128 + row0]);
        float inv1 = 1.f / (lsum[row0 + 8] + lsum[128 + row0 + 8]);
        const float* src = red + wm * 2048;
        __half* o0 = g_attn + (size_t)(bm * 128 + row0) * QS + h * 128;
        __half* o1 = g_attn + (size_t)(bm * 128 + row0 + 8) * QS + h * 128;
#pragma unroll
        for (int dn = 0; dn < 16; dn++) {
            int nc = dn * 8 + 2 * c;
            float2 s0 = *(const float2*)(src + r * 128 + nc);
            float2 s1 = *(const float2*)(src + (r + 8) * 128 + nc);
            *(__half2*)(o0 + nc) = __floats2half2_rn((acc_o[dn][0] + s0.x) * inv0,
                                                     (acc_o[dn][1] + s0.y) * inv0);
            *(__half2*)(o1 + nc) = __floats2half2_rn((acc_o[dn][2] + s1.x) * inv1,
                                                     (acc_o[dn][3] + s1.y) * inv1);
        }
    }
}

// ---------------- fp32 -> fp16 conversion (all three arrays, one launch) ----------------
#define N4_HID  (TT * HIDDEN / 4)
#define N4_WQKV (QKVN * HIDDEN / 4)
#define N4_WO   (HIDDEN * QS / 4)
__global__ void h_conv_all(const float4* __restrict__ s0, uint2* __restrict__ d0,
                           const float4* __restrict__ s1, uint2* __restrict__ d1,
                           const float4* __restrict__ s2, uint2* __restrict__ d2) {
    int i = blockIdx.x * 256 + threadIdx.x;
    int stride = gridDim.x * 256;
    int ntot = N4_HID + N4_WQKV + N4_WO;
    for (; i < ntot; i += stride) {
        const float4* s; uint2* d; int idx;
        if (i < N4_HID)              { s = s0; d = d0; idx = i; }
        else if (i < N4_HID + N4_WQKV) { s = s1; d = d1; idx = i - N4_HID; }
        else                         { s = s2; d = d2; idx = i - N4_HID - N4_WQKV; }
        float4 v = s[idx];
        __half2 lo = __floats2half2_rn(v.x, v.y);
        __half2 hi = __floats2half2_rn(v.z, v.w);
        uint2 o;
        o.x = *(unsigned*)&lo;
        o.y = *(unsigned*)&hi;
        d[idx] = o;
    }
}

// ---------------- inv_freq ----------------
__global__ void init_invf() {
    int i = threadIdx.x;
    if (i < 64)
        g_invf[i] = (float)exp(-(double)i * (log(10000.0) / 64.0));
}

// ---------------- launcher ----------------
extern "C" void kernel_launch(void* const* d_in, const int* in_sizes, int n_in,
                              void* d_out, int out_size)
{
    const int* positions = (const int*)d_in[0];   // int32 (JAX x64 disabled)
    const float* hidden = (const float*)d_in[1];
    const float* w_qkv  = (const float*)d_in[2];
    const float* w_o    = (const float*)d_in[3];
    const float* qw     = (const float*)d_in[4];
    const float* kw     = (const float*)d_in[5];
    float* out = (float*)d_out;

    __half *p_attn, *p_hidh, *p_wqkvh, *p_woh;
    cudaGetSymbolAddress((void**)&p_attn,  g_attn);
    cudaGetSymbolAddress((void**)&p_hidh,  g_hidh);
    cudaGetSymbolAddress((void**)&p_wqkvh, g_wqkvh);
    cudaGetSymbolAddress((void**)&p_woh,   g_woh);

    cudaFuncSetAttribute(gemm_h, cudaFuncAttributeMaxDynamicSharedMemorySize, SM_TOT);
    cudaFuncSetAttribute(flash_kernel, cudaFuncAttributeMaxDynamicSharedMemorySize, FSM_TOT);

    init_invf<<<1, 64>>>();

    // 0) fp16 conversions (one launch)
    h_conv_all<<<2048, 256>>>((const float4*)hidden, (uint2*)p_hidh,
                              (const float4*)w_qkv,  (uint2*)p_wqkvh,
                              (const float4*)w_o,    (uint2*)p_woh);

    // 1) QKV projection with fused RMSNorm+RoPE+reorder epilogue
    gemm_h<<<dim3(QKVN / BN, TT / BM, 1), 256, SM_TOT>>>(
        p_hidh, p_wqkvh, nullptr, HIDDEN, HIDDEN, HIDDEN, 0, 1.0f,
        positions, qw, kw, 1);

    // 2) fused flash attention -> g_attn (fp16)
    flash_kernel<<<512, 512, FSM_TOT>>>();

    // 3) output projection (fp32 out)
    gemm_h<<<dim3(HIDDEN / BN, TT / BM, 1), 256, SM_TOT>>>(
        p_attn, p_woh, out, QS, QS, QS, HIDDEN, 1.0f,
        nullptr, nullptr, nullptr, 0);
}